// round 1
// baseline (speedup 1.0000x reference)
#include <cuda_runtime.h>

// Problem constants (fixed shapes from setup_inputs)
#define BTOT   4096      // number of windows (B_)
#define SEQ    49        // tokens per window (7x7)
#define EMB    512       // model dim
#define NH     16        // heads
#define HD     32        // head dim
#define FL     16        // frame_len
#define NWIN   64        // windows per frame  (B_/(bs*fl))
#define QKVN   1536      // 3*EMB
#define MROWS  (BTOT*SEQ)   // 200704

// Scratch (static device globals — allocation-free)
__device__ float g_qkv[(size_t)MROWS * QKVN];   // [B_, N, 3, H, c]  ~1.23 GB
__device__ float g_att[(size_t)MROWS * EMB];    // [B_, N, H, c]     ~0.41 GB

__constant__ int c_shift[9] = {-4, 1, 2, -1, 0, 3, -2, -3, 4};

// ---------------------------------------------------------------------------
// SGEMM (NT): C[m,n] = sum_k A[m,k] * B[n,k] (+ bias[n])
// 128x128 block tile, BK=8, 256 threads, 8x8 per-thread micro tile.
// M,N,K all divisible by tile sizes for our shapes.
// ---------------------------------------------------------------------------
template <int WITH_BIAS>
__global__ __launch_bounds__(256) void sgemm_nt(
    const float* __restrict__ A, const float* __restrict__ B,
    const float* __restrict__ bias, float* __restrict__ C,
    int M, int N, int K)
{
    __shared__ float As[8][128];
    __shared__ float Bs[8][128];

    const int bm  = blockIdx.y * 128;
    const int bn  = blockIdx.x * 128;
    const int tid = threadIdx.x;

    // load mapping: 128 rows x 8 cols per tile = 256 float4
    const int lr = tid >> 1;          // 0..127
    const int lc = (tid & 1) << 2;    // 0 or 4
    // compute mapping: 16x16 thread grid, each owns 8x8 outputs
    const int tx = tid & 15;
    const int ty = tid >> 4;

    const float* Ab = A + (size_t)(bm + lr) * K + lc;
    const float* Bb = B + (size_t)(bn + lr) * K + lc;

    float acc[8][8];
#pragma unroll
    for (int i = 0; i < 8; i++)
#pragma unroll
        for (int j = 0; j < 8; j++) acc[i][j] = 0.f;

    for (int k0 = 0; k0 < K; k0 += 8) {
        float4 av = *reinterpret_cast<const float4*>(Ab + k0);
        float4 bv = *reinterpret_cast<const float4*>(Bb + k0);
        As[lc + 0][lr] = av.x; As[lc + 1][lr] = av.y;
        As[lc + 2][lr] = av.z; As[lc + 3][lr] = av.w;
        Bs[lc + 0][lr] = bv.x; Bs[lc + 1][lr] = bv.y;
        Bs[lc + 2][lr] = bv.z; Bs[lc + 3][lr] = bv.w;
        __syncthreads();

#pragma unroll
        for (int kk = 0; kk < 8; kk++) {
            float a[8], b[8];
            *reinterpret_cast<float4*>(&a[0]) = *reinterpret_cast<const float4*>(&As[kk][ty * 8]);
            *reinterpret_cast<float4*>(&a[4]) = *reinterpret_cast<const float4*>(&As[kk][ty * 8 + 4]);
            *reinterpret_cast<float4*>(&b[0]) = *reinterpret_cast<const float4*>(&Bs[kk][tx * 8]);
            *reinterpret_cast<float4*>(&b[4]) = *reinterpret_cast<const float4*>(&Bs[kk][tx * 8 + 4]);
#pragma unroll
            for (int i = 0; i < 8; i++)
#pragma unroll
                for (int j = 0; j < 8; j++)
                    acc[i][j] += a[i] * b[j];
        }
        __syncthreads();
    }

#pragma unroll
    for (int i = 0; i < 8; i++) {
        const int row = bm + ty * 8 + i;
        float* Crow = C + (size_t)row * N + bn + tx * 8;
#pragma unroll
        for (int j = 0; j < 8; j += 4) {
            float4 o;
            o.x = acc[i][j + 0];
            o.y = acc[i][j + 1];
            o.z = acc[i][j + 2];
            o.w = acc[i][j + 3];
            if (WITH_BIAS) {
                const float* bp = bias + bn + tx * 8 + j;
                o.x += bp[0]; o.y += bp[1]; o.z += bp[2]; o.w += bp[3];
            }
            *reinterpret_cast<float4*>(Crow + j) = o;
        }
    }
}

// ---------------------------------------------------------------------------
// Fused shift-gather + attention + inverse-shift scatter.
// One block per (window b, head h). Key identity: the forward shift for
// window frame t' at spatial position n reads frame (t'-s[n]) mod FL, and the
// inverse shift routes the output of (t', n) back to the SAME frame. So the
// gather rows and scatter rows coincide (srow[n]).
// ---------------------------------------------------------------------------
#define QSTR 33  // padded stride to kill 32-way smem bank conflicts

__global__ __launch_bounds__(128) void attn_kernel(
    const float* __restrict__ bias_table,   // [169, NH]
    const int*   __restrict__ rel_index,    // [SEQ, SEQ]
    float*       __restrict__ outbuf)       // g_att
{
    const int b   = blockIdx.x;   // window row in [0, BTOT)
    const int h   = blockIdx.y;   // head
    const int tid = threadIdx.x;  // 128 threads

    __shared__ float qs[SEQ * QSTR];
    __shared__ float ks[SEQ * QSTR];
    __shared__ float vs[SEQ * QSTR];
    __shared__ float sc[SEQ * SEQ];
    __shared__ int   srow[SEQ];

    const int t = (b / NWIN) % FL;

    if (tid < SEQ) {
        const int i = tid / 7, j = tid % 7;
        const int s = c_shift[(i % 3) * 3 + (j % 3)];
        const int tsrc = (t - s + 2 * FL) % FL;
        srow[tid] = b + (tsrc - t) * NWIN;
    }
    __syncthreads();

    // gather q/k/v (shifted rows), head h slice
    for (int idx = tid; idx < SEQ * HD; idx += 128) {
        const int n = idx / HD, c = idx % HD;
        const size_t base = ((size_t)srow[n] * SEQ + n) * QKVN + h * HD + c;
        const int sm = n * QSTR + c;
        qs[sm] = g_qkv[base];
        ks[sm] = g_qkv[base + EMB];
        vs[sm] = g_qkv[base + 2 * EMB];
    }
    __syncthreads();

    const float scale = 0.1767766952966369f;  // 32^-0.5

    // scores + relative position bias
    for (int idx = tid; idx < SEQ * SEQ; idx += 128) {
        const int n = idx / SEQ, m = idx % SEQ;
        float acc = 0.f;
#pragma unroll
        for (int c = 0; c < HD; c++)
            acc += qs[n * QSTR + c] * ks[m * QSTR + c];
        sc[idx] = acc * scale + bias_table[rel_index[idx] * NH + h];
    }
    __syncthreads();

    // softmax: one thread per row (49 active)
    if (tid < SEQ) {
        float mx = -1e30f;
#pragma unroll 7
        for (int m = 0; m < SEQ; m++) mx = fmaxf(mx, sc[tid * SEQ + m]);
        float sum = 0.f;
#pragma unroll 7
        for (int m = 0; m < SEQ; m++) {
            const float e = expf(sc[tid * SEQ + m] - mx);
            sc[tid * SEQ + m] = e;
            sum += e;
        }
        const float inv = 1.f / sum;
#pragma unroll 7
        for (int m = 0; m < SEQ; m++) sc[tid * SEQ + m] *= inv;
    }
    __syncthreads();

    // O = P @ V, scatter with inverse shift (same rows as gather)
    for (int idx = tid; idx < SEQ * HD; idx += 128) {
        const int n = idx / HD, c = idx % HD;
        float acc = 0.f;
#pragma unroll 7
        for (int m = 0; m < SEQ; m++)
            acc += sc[n * SEQ + m] * vs[m * QSTR + c];
        outbuf[((size_t)srow[n] * SEQ + n) * EMB + h * HD + c] = acc;
    }
}

// ---------------------------------------------------------------------------
extern "C" void kernel_launch(void* const* d_in, const int* in_sizes, int n_in,
                              void* d_out, int out_size)
{
    const float* x          = (const float*)d_in[0];   // [4096,49,512]
    const float* qkv_w      = (const float*)d_in[1];   // [1536,512]
    const float* proj_w     = (const float*)d_in[2];   // [512,512]
    const float* proj_b     = (const float*)d_in[3];   // [512]
    const float* bias_table = (const float*)d_in[4];   // [169,16]
    const int*   rel_index  = (const int*)d_in[5];     // [49,49]
    float* out = (float*)d_out;

    float* qkvbuf = nullptr;
    float* attbuf = nullptr;
    cudaGetSymbolAddress((void**)&qkvbuf, g_qkv);
    cudaGetSymbolAddress((void**)&attbuf, g_att);

    // K1: qkv = x @ qkv_w^T   [200704,512]x[1536,512]^T
    {
        dim3 grid(QKVN / 128, MROWS / 128);
        sgemm_nt<0><<<grid, 256>>>(x, qkv_w, nullptr, qkvbuf, MROWS, QKVN, EMB);
    }

    // K2: fused shift + attention + inverse shift
    {
        dim3 grid(BTOT, NH);
        attn_kernel<<<grid, 128>>>(bias_table, rel_index, attbuf);
    }

    // K3: out = att @ proj_w^T + proj_b   [200704,512]x[512,512]^T
    {
        dim3 grid(EMB / 128, MROWS / 128);
        sgemm_nt<1><<<grid, 256>>>(attbuf, proj_w, proj_b, out, MROWS, EMB, EMB);
    }
}

// round 3
// speedup vs baseline: 1.4787x; 1.4787x over previous
#include <cuda_runtime.h>
#include <cuda_bf16.h>
#include <cstdint>

// Problem constants
#define BTOT   4096
#define SEQ    49
#define EMB    512
#define NH     16
#define HD     32
#define FL     16
#define NWIN   64
#define QKVN   1536
#define MROWS  (BTOT*SEQ)   // 200704

__device__ float g_qkv[(size_t)MROWS * QKVN];
__device__ float g_att[(size_t)MROWS * EMB];
__constant__ int c_shift[9] = {-4, 1, 2, -1, 0, 3, -2, -3, 4};

// ---------------------------------------------------------------------------
// Split-bf16 (3xBF16) tensor-core GEMM (NT): C = A @ B^T (+bias)
// 128x128x32 block tile, 8 warps (4x2), warp tile 32x64, m16n8k16 bf16 mma,
// fp32 accumulate. Each fp32 operand split hi/lo bf16; acc += hi*hi+lo*hi+hi*lo.
// cp.async double-buffered fp32 smem tiles, stride 40 (conflict-free float2).
// ---------------------------------------------------------------------------
#define BM 128
#define BN 128
#define BK 32
#define KST 40
#define AFLTS (BM * KST)
#define BUFSZ (2 * BM * KST)

__device__ __forceinline__ void mma_bf16(float* d, const uint32_t* a, const uint32_t* b) {
    asm volatile(
        "mma.sync.aligned.m16n8k16.row.col.f32.bf16.bf16.f32 "
        "{%0,%1,%2,%3}, {%4,%5,%6,%7}, {%8,%9}, {%0,%1,%2,%3};\n"
        : "+f"(d[0]), "+f"(d[1]), "+f"(d[2]), "+f"(d[3])
        : "r"(a[0]), "r"(a[1]), "r"(a[2]), "r"(a[3]), "r"(b[0]), "r"(b[1]));
}
__device__ __forceinline__ void cp_async16(uint32_t s, const void* g) {
    asm volatile("cp.async.cg.shared.global [%0], [%1], 16;\n" :: "r"(s), "l"(g));
}
__device__ __forceinline__ void cp_commit() { asm volatile("cp.async.commit_group;\n"); }
__device__ __forceinline__ void cp_wait0()  { asm volatile("cp.async.wait_group 0;\n"); }

__device__ __forceinline__ void split2(float2 v, uint32_t& hi, uint32_t& lo) {
    __nv_bfloat16 hx = __float2bfloat16_rn(v.x);
    __nv_bfloat16 hy = __float2bfloat16_rn(v.y);
    __nv_bfloat16 lx = __float2bfloat16_rn(v.x - __bfloat162float(hx));
    __nv_bfloat16 ly = __float2bfloat16_rn(v.y - __bfloat162float(hy));
    hi = ((uint32_t)__bfloat16_as_ushort(hy) << 16) | (uint32_t)__bfloat16_as_ushort(hx);
    lo = ((uint32_t)__bfloat16_as_ushort(ly) << 16) | (uint32_t)__bfloat16_as_ushort(lx);
}

template <int WITH_BIAS>
__global__ __launch_bounds__(256) void gemm_3xbf16_nt(
    const float* __restrict__ A, const float* __restrict__ B,
    const float* __restrict__ bias, float* __restrict__ C,
    int M, int N, int K)
{
    extern __shared__ float smem[];
    const uint32_t smem_u32 = (uint32_t)__cvta_generic_to_shared(smem);

    const int tid    = threadIdx.x;
    const int lane   = tid & 31;
    const int wid    = tid >> 5;
    const int warp_m = wid >> 1;
    const int warp_n = wid & 1;
    const int lr     = lane >> 2;   // 0..7
    const int lc2    = (lane & 3) * 2;  // 0,2,4,6

    const int bm = blockIdx.y * BM;
    const int bn = blockIdx.x * BN;

    const int l_row0 = tid >> 3;
    const int l_kc   = (tid & 7) * 4;

    const float* Agp = A + (size_t)(bm + l_row0) * K + l_kc;
    const float* Bgp = B + (size_t)(bn + l_row0) * K + l_kc;

    auto load_chunk = [&](int k0, int buf) {
        const uint32_t sa = smem_u32 + (uint32_t)(buf * BUFSZ) * 4u;
        const uint32_t sb = sa + (uint32_t)AFLTS * 4u;
#pragma unroll
        for (int p = 0; p < 4; p++) {
            const int row = l_row0 + p * 32;
            cp_async16(sa + (uint32_t)(row * KST + l_kc) * 4u, Agp + (size_t)(p * 32) * K + k0);
            cp_async16(sb + (uint32_t)(row * KST + l_kc) * 4u, Bgp + (size_t)(p * 32) * K + k0);
        }
    };

    float acc[2][8][4];
#pragma unroll
    for (int mt = 0; mt < 2; mt++)
#pragma unroll
        for (int nt = 0; nt < 8; nt++)
#pragma unroll
            for (int r = 0; r < 4; r++) acc[mt][nt][r] = 0.f;

    const int nchunk = K / BK;
    load_chunk(0, 0);
    cp_commit();

    for (int i = 0; i < nchunk; i++) {
        cp_wait0();
        __syncthreads();
        if (i + 1 < nchunk) { load_chunk((i + 1) * BK, (i + 1) & 1); cp_commit(); }

        const float* sA = smem + (i & 1) * BUFSZ;
        const float* sB = sA + AFLTS;

#pragma unroll
        for (int kk = 0; kk < BK; kk += 16) {
            uint32_t ah[2][4], al[2][4];
#pragma unroll
            for (int mt = 0; mt < 2; mt++) {
                const int r = warp_m * 32 + mt * 16 + lr;
                float2 x0 = *reinterpret_cast<const float2*>(&sA[(r    ) * KST + kk + lc2]);
                float2 x1 = *reinterpret_cast<const float2*>(&sA[(r + 8) * KST + kk + lc2]);
                float2 x2 = *reinterpret_cast<const float2*>(&sA[(r    ) * KST + kk + lc2 + 8]);
                float2 x3 = *reinterpret_cast<const float2*>(&sA[(r + 8) * KST + kk + lc2 + 8]);
                split2(x0, ah[mt][0], al[mt][0]);
                split2(x1, ah[mt][1], al[mt][1]);
                split2(x2, ah[mt][2], al[mt][2]);
                split2(x3, ah[mt][3], al[mt][3]);
            }
#pragma unroll
            for (int nt = 0; nt < 8; nt++) {
                const int n = warp_n * 64 + nt * 8 + lr;
                float2 y0 = *reinterpret_cast<const float2*>(&sB[n * KST + kk + lc2]);
                float2 y1 = *reinterpret_cast<const float2*>(&sB[n * KST + kk + lc2 + 8]);
                uint32_t bh[2], bl[2];
                split2(y0, bh[0], bl[0]);
                split2(y1, bh[1], bl[1]);
#pragma unroll
                for (int mt = 0; mt < 2; mt++) {
                    mma_bf16(acc[mt][nt], ah[mt], bh);
                    mma_bf16(acc[mt][nt], al[mt], bh);
                    mma_bf16(acc[mt][nt], ah[mt], bl);
                }
            }
        }
        __syncthreads();
    }

    // epilogue (acc layout: c0,c1 -> row lr, cols 2c,2c+1 ; c2,c3 -> row lr+8)
#pragma unroll
    for (int mt = 0; mt < 2; mt++) {
        const int row0 = bm + warp_m * 32 + mt * 16 + lr;
#pragma unroll
        for (int nt = 0; nt < 8; nt++) {
            const int col = bn + warp_n * 64 + nt * 8 + lc2;
            float2 v0 = make_float2(acc[mt][nt][0], acc[mt][nt][1]);
            float2 v1 = make_float2(acc[mt][nt][2], acc[mt][nt][3]);
            if (WITH_BIAS) {
                v0.x += bias[col]; v0.y += bias[col + 1];
                v1.x += bias[col]; v1.y += bias[col + 1];
            }
            *reinterpret_cast<float2*>(C + (size_t)row0 * N + col)       = v0;
            *reinterpret_cast<float2*>(C + (size_t)(row0 + 8) * N + col) = v1;
        }
    }
}

// ---------------------------------------------------------------------------
// Fused shift-gather + attention + inverse-shift scatter
// (gather rows == scatter rows identity)
// ---------------------------------------------------------------------------
#define QSTR 33

__global__ __launch_bounds__(128) void attn_kernel(
    const float* __restrict__ bias_table,
    const int*   __restrict__ rel_index,
    float*       __restrict__ outbuf)
{
    const int b   = blockIdx.x;
    const int h   = blockIdx.y;
    const int tid = threadIdx.x;

    __shared__ float qs[SEQ * QSTR];
    __shared__ float ks[SEQ * QSTR];
    __shared__ float vs[SEQ * QSTR];
    __shared__ float sc[SEQ * SEQ];
    __shared__ int   srow[SEQ];

    const int t = (b / NWIN) % FL;

    if (tid < SEQ) {
        const int i = tid / 7, j = tid % 7;
        const int s = c_shift[(i % 3) * 3 + (j % 3)];
        const int tsrc = (t - s + 2 * FL) % FL;
        srow[tid] = b + (tsrc - t) * NWIN;
    }
    __syncthreads();

    for (int idx = tid; idx < SEQ * HD; idx += 128) {
        const int n = idx / HD, c = idx % HD;
        const size_t base = ((size_t)srow[n] * SEQ + n) * QKVN + h * HD + c;
        const int sm = n * QSTR + c;
        qs[sm] = g_qkv[base];
        ks[sm] = g_qkv[base + EMB];
        vs[sm] = g_qkv[base + 2 * EMB];
    }
    __syncthreads();

    const float scale = 0.1767766952966369f;

    for (int idx = tid; idx < SEQ * SEQ; idx += 128) {
        const int n = idx / SEQ, m = idx % SEQ;
        float acc = 0.f;
#pragma unroll
        for (int c = 0; c < HD; c++)
            acc += qs[n * QSTR + c] * ks[m * QSTR + c];
        sc[idx] = acc * scale + bias_table[rel_index[idx] * NH + h];
    }
    __syncthreads();

    if (tid < SEQ) {
        float mx = -1e30f;
#pragma unroll 7
        for (int m = 0; m < SEQ; m++) mx = fmaxf(mx, sc[tid * SEQ + m]);
        float sum = 0.f;
#pragma unroll 7
        for (int m = 0; m < SEQ; m++) {
            const float e = expf(sc[tid * SEQ + m] - mx);
            sc[tid * SEQ + m] = e;
            sum += e;
        }
        const float inv = 1.f / sum;
#pragma unroll 7
        for (int m = 0; m < SEQ; m++) sc[tid * SEQ + m] *= inv;
    }
    __syncthreads();

    for (int idx = tid; idx < SEQ * HD; idx += 128) {
        const int n = idx / HD, c = idx % HD;
        float acc = 0.f;
#pragma unroll 7
        for (int m = 0; m < SEQ; m++)
            acc += sc[n * SEQ + m] * vs[m * QSTR + c];
        outbuf[((size_t)srow[n] * SEQ + n) * EMB + h * HD + c] = acc;
    }
}

// ---------------------------------------------------------------------------
extern "C" void kernel_launch(void* const* d_in, const int* in_sizes, int n_in,
                              void* d_out, int out_size)
{
    const float* x          = (const float*)d_in[0];
    const float* qkv_w      = (const float*)d_in[1];
    const float* proj_w     = (const float*)d_in[2];
    const float* proj_b     = (const float*)d_in[3];
    const float* bias_table = (const float*)d_in[4];
    const int*   rel_index  = (const int*)d_in[5];
    float* out = (float*)d_out;

    float* qkvbuf = nullptr;
    float* attbuf = nullptr;
    cudaGetSymbolAddress((void**)&qkvbuf, g_qkv);
    cudaGetSymbolAddress((void**)&attbuf, g_att);

    const int smem_bytes = 2 * BUFSZ * (int)sizeof(float);   // 81920
    cudaFuncSetAttribute(gemm_3xbf16_nt<0>, cudaFuncAttributeMaxDynamicSharedMemorySize, smem_bytes);
    cudaFuncSetAttribute(gemm_3xbf16_nt<1>, cudaFuncAttributeMaxDynamicSharedMemorySize, smem_bytes);

    // K1: qkv = x @ qkv_w^T
    {
        dim3 grid(QKVN / BN, MROWS / BM);
        gemm_3xbf16_nt<0><<<grid, 256, smem_bytes>>>(x, qkv_w, nullptr, qkvbuf, MROWS, QKVN, EMB);
    }
    // K2: fused shift + attention + inverse shift
    {
        dim3 grid(BTOT, NH);
        attn_kernel<<<grid, 128>>>(bias_table, rel_index, attbuf);
    }
    // K3: out = att @ proj_w^T + proj_b
    {
        dim3 grid(EMB / BN, MROWS / BM);
        gemm_3xbf16_nt<1><<<grid, 256, smem_bytes>>>(attbuf, proj_w, proj_b, out, MROWS, EMB, EMB);
    }
}

// round 6
// speedup vs baseline: 1.9456x; 1.3158x over previous
#include <cuda_runtime.h>
#include <cuda_bf16.h>
#include <cstdint>

// Problem constants
#define BTOT   4096
#define SEQ    49
#define EMB    512
#define NH     16
#define HD     32
#define FL     16
#define NWIN   64
#define QKVN   1536
#define MROWS  (BTOT*SEQ)   // 200704

// Scratch (static device globals)
__device__ float         g_qkv[(size_t)MROWS * QKVN];
__device__ __nv_bfloat16 g_xhi[(size_t)MROWS * EMB];
__device__ __nv_bfloat16 g_xlo[(size_t)MROWS * EMB];
__device__ __nv_bfloat16 g_ahi[(size_t)MROWS * EMB];
__device__ __nv_bfloat16 g_alo[(size_t)MROWS * EMB];
__device__ __nv_bfloat16 g_w1hi[QKVN * EMB];
__device__ __nv_bfloat16 g_w1lo[QKVN * EMB];
__device__ __nv_bfloat16 g_w2hi[EMB * EMB];
__device__ __nv_bfloat16 g_w2lo[EMB * EMB];

__constant__ int c_shift[9] = {-4, 1, 2, -1, 0, 3, -2, -3, 4};

// ---------------------------------------------------------------------------
__device__ __forceinline__ uint32_t smem_u32(const void* p) {
    uint32_t a;
    asm("{ .reg .u64 t; cvta.to.shared.u64 t, %1; cvt.u32.u64 %0, t; }" : "=r"(a) : "l"(p));
    return a;
}
__device__ __forceinline__ void cp_async16(uint32_t s, const void* g) {
    asm volatile("cp.async.cg.shared.global [%0], [%1], 16;\n" :: "r"(s), "l"(g));
}
__device__ __forceinline__ void cp_commit() { asm volatile("cp.async.commit_group;\n"); }
__device__ __forceinline__ void cp_wait0()  { asm volatile("cp.async.wait_group 0;\n"); }

__device__ __forceinline__ void mma_bf16(float* d, const uint32_t* a, const uint32_t* b) {
    asm volatile(
        "mma.sync.aligned.m16n8k16.row.col.f32.bf16.bf16.f32 "
        "{%0,%1,%2,%3}, {%4,%5,%6,%7}, {%8,%9}, {%0,%1,%2,%3};\n"
        : "+f"(d[0]), "+f"(d[1]), "+f"(d[2]), "+f"(d[3])
        : "r"(a[0]), "r"(a[1]), "r"(a[2]), "r"(a[3]), "r"(b[0]), "r"(b[1]));
}
__device__ __forceinline__ void ldsm_x4(uint32_t* r, uint32_t addr) {
    asm volatile("ldmatrix.sync.aligned.m8n8.x4.shared.b16 {%0,%1,%2,%3}, [%4];\n"
                 : "=r"(r[0]), "=r"(r[1]), "=r"(r[2]), "=r"(r[3]) : "r"(addr));
}

// ---------------------------------------------------------------------------
// Split fp32 -> (hi, lo) bf16
// ---------------------------------------------------------------------------
__global__ void split_kernel(const float* __restrict__ in,
                             __nv_bfloat16* __restrict__ hi,
                             __nv_bfloat16* __restrict__ lo, int n4)
{
    const int i = blockIdx.x * blockDim.x + threadIdx.x;
    if (i >= n4) return;
    float4 v = reinterpret_cast<const float4*>(in)[i];
    __nv_bfloat16 h0 = __float2bfloat16_rn(v.x);
    __nv_bfloat16 h1 = __float2bfloat16_rn(v.y);
    __nv_bfloat16 h2 = __float2bfloat16_rn(v.z);
    __nv_bfloat16 h3 = __float2bfloat16_rn(v.w);
    __nv_bfloat162* hp = reinterpret_cast<__nv_bfloat162*>(hi);
    __nv_bfloat162* lp = reinterpret_cast<__nv_bfloat162*>(lo);
    hp[2 * i]     = __nv_bfloat162(h0, h1);
    hp[2 * i + 1] = __nv_bfloat162(h2, h3);
    lp[2 * i]     = __nv_bfloat162(__float2bfloat16_rn(v.x - __bfloat162float(h0)),
                                   __float2bfloat16_rn(v.y - __bfloat162float(h1)));
    lp[2 * i + 1] = __nv_bfloat162(__float2bfloat16_rn(v.z - __bfloat162float(h2)),
                                   __float2bfloat16_rn(v.w - __bfloat162float(h3)));
}

// ---------------------------------------------------------------------------
// 3xBF16 tensor-core GEMM (NT), bf16 hi/lo operands pre-split in global mem.
// 128x128 block tile, BK=32, 8 warps (4x2), warp tile 32x64, m16n8k16 mma.
// smem tiles: bf16, 80B row stride (5r mod 8 => conflict-free ldmatrix).
// cp.async double-buffered. 2 CTAs/SM.
// ---------------------------------------------------------------------------
#define BK     32
#define RSTR   80                       // bytes per smem row (64 data + 16 pad)
#define TILEB  (128 * RSTR)             // 10240 B per tile
#define BUFB   (4 * TILEB)              // Ahi, Alo, Bhi, Blo
#define GSMEM  (2 * BUFB)               // 81920 B

template <int WITH_BIAS>
__global__ __launch_bounds__(256, 2) void gemm_3xbf16(
    const __nv_bfloat16* __restrict__ Ahi, const __nv_bfloat16* __restrict__ Alo,
    const __nv_bfloat16* __restrict__ Bhi, const __nv_bfloat16* __restrict__ Blo,
    const float* __restrict__ bias, float* __restrict__ C, int N)
{
    extern __shared__ unsigned char dsmem[];
    const uint32_t sbase = smem_u32(dsmem);

    const int tid    = threadIdx.x;
    const int lane   = tid & 31;
    const int wid    = tid >> 5;
    const int warp_m = wid >> 1;       // 0..3
    const int warp_n = wid & 1;        // 0..1
    const int bm = blockIdx.y * 128;
    const int bn = blockIdx.x * 128;

    // ---- cp.async mapping: row = tid>>1 (0..127), 2 segs of 16B per tile ----
    const int lrow = tid >> 1;
    const int seg0 = (tid & 1) * 2;
    const __nv_bfloat16* gAh = Ahi + (size_t)(bm + lrow) * EMB;
    const __nv_bfloat16* gAl = Alo + (size_t)(bm + lrow) * EMB;
    const __nv_bfloat16* gBh = Bhi + (size_t)(bn + lrow) * EMB;
    const __nv_bfloat16* gBl = Blo + (size_t)(bn + lrow) * EMB;

    auto load_chunk = [&](int ch, int buf) {
        const uint32_t dst = sbase + buf * BUFB + lrow * RSTR;
        const int gb = ch * (BK * 2);   // global byte offset into K
#pragma unroll
        for (int s = 0; s < 2; s++) {
            const int sb = (seg0 + s) * 16;
            cp_async16(dst + sb,             (const char*)gAh + gb + sb);
            cp_async16(dst + TILEB + sb,     (const char*)gAl + gb + sb);
            cp_async16(dst + 2 * TILEB + sb, (const char*)gBh + gb + sb);
            cp_async16(dst + 3 * TILEB + sb, (const char*)gBl + gb + sb);
        }
    };

    // ---- ldmatrix per-lane offsets ----
    // A (x4): rows 0..15 of a m16 tile, 16B col chunks
    const uint32_t a_off = (uint32_t)((warp_m * 32 + (lane & 15)) * RSTR + (lane >> 4) * 16);
    // B (x4): covers 16 cols (2 n-groups of 8): lanes 0-7 n0-7/k0, 8-15 n0-7/k8,
    // 16-23 n8-15/k0, 24-31 n8-15/k8
    const uint32_t b_off = (uint32_t)((warp_n * 64 + (lane & 7) + ((lane >> 4) << 3)) * RSTR
                                      + ((lane >> 3) & 1) * 16);

    float acc[2][8][4];
#pragma unroll
    for (int mt = 0; mt < 2; mt++)
#pragma unroll
        for (int nt = 0; nt < 8; nt++)
#pragma unroll
            for (int r = 0; r < 4; r++) acc[mt][nt][r] = 0.f;

    const int nchunk = EMB / BK;   // 16
    load_chunk(0, 0);
    cp_commit();

    for (int i = 0; i < nchunk; i++) {
        cp_wait0();
        __syncthreads();
        if (i + 1 < nchunk) { load_chunk(i + 1, (i + 1) & 1); cp_commit(); }

        const uint32_t base = sbase + (i & 1) * BUFB;

#pragma unroll
        for (int kk = 0; kk < 2; kk++) {
            const uint32_t kb = kk * 32;   // 16 k-values = 32B
            uint32_t ah[2][4], al[2][4];
#pragma unroll
            for (int mt = 0; mt < 2; mt++) {
                ldsm_x4(ah[mt], base + a_off + mt * (16 * RSTR) + kb);
                ldsm_x4(al[mt], base + TILEB + a_off + mt * (16 * RSTR) + kb);
            }
#pragma unroll
            for (int ng = 0; ng < 4; ng++) {
                uint32_t bh[4], bl[4];
                ldsm_x4(bh, base + 2 * TILEB + b_off + ng * (16 * RSTR) + kb);
                ldsm_x4(bl, base + 3 * TILEB + b_off + ng * (16 * RSTR) + kb);
#pragma unroll
                for (int j = 0; j < 2; j++) {
                    const int nt = 2 * ng + j;
#pragma unroll
                    for (int mt = 0; mt < 2; mt++) {
                        mma_bf16(acc[mt][nt], ah[mt], bh + 2 * j);
                        mma_bf16(acc[mt][nt], al[mt], bh + 2 * j);
                        mma_bf16(acc[mt][nt], ah[mt], bl + 2 * j);
                    }
                }
            }
        }
        __syncthreads();
    }

    // ---- epilogue ----
    const int lr  = lane >> 2;
    const int lc2 = (lane & 3) * 2;
#pragma unroll
    for (int mt = 0; mt < 2; mt++) {
        const int row0 = bm + warp_m * 32 + mt * 16 + lr;
#pragma unroll
        for (int nt = 0; nt < 8; nt++) {
            const int col = bn + warp_n * 64 + nt * 8 + lc2;
            float2 v0 = make_float2(acc[mt][nt][0], acc[mt][nt][1]);
            float2 v1 = make_float2(acc[mt][nt][2], acc[mt][nt][3]);
            if (WITH_BIAS) {
                v0.x += bias[col]; v0.y += bias[col + 1];
                v1.x += bias[col]; v1.y += bias[col + 1];
            }
            *reinterpret_cast<float2*>(C + (size_t)row0 * N + col)       = v0;
            *reinterpret_cast<float2*>(C + (size_t)(row0 + 8) * N + col) = v1;
        }
    }
}

// ---------------------------------------------------------------------------
// Fused shift-gather + attention + inverse-shift scatter.
// Emits hi/lo bf16 directly (feeds K3 GEMM A operand).
// ---------------------------------------------------------------------------
#define QSTR 33

__global__ __launch_bounds__(128) void attn_kernel(
    const float* __restrict__ bias_table,
    const int*   __restrict__ rel_index)
{
    const int b   = blockIdx.x;
    const int h   = blockIdx.y;
    const int tid = threadIdx.x;

    __shared__ float qs[SEQ * QSTR];
    __shared__ float ks[SEQ * QSTR];
    __shared__ float vs[SEQ * QSTR];
    __shared__ float sc[SEQ * SEQ];
    __shared__ int   srow[SEQ];

    const int t = (b / NWIN) % FL;

    if (tid < SEQ) {
        const int i = tid / 7, j = tid % 7;
        const int s = c_shift[(i % 3) * 3 + (j % 3)];
        const int tsrc = (t - s + 2 * FL) % FL;
        srow[tid] = b + (tsrc - t) * NWIN;
    }
    __syncthreads();

    for (int idx = tid; idx < SEQ * HD; idx += 128) {
        const int n = idx / HD, c = idx % HD;
        const size_t base = ((size_t)srow[n] * SEQ + n) * QKVN + h * HD + c;
        const int sm = n * QSTR + c;
        qs[sm] = g_qkv[base];
        ks[sm] = g_qkv[base + EMB];
        vs[sm] = g_qkv[base + 2 * EMB];
    }
    __syncthreads();

    const float scale = 0.1767766952966369f;

    for (int idx = tid; idx < SEQ * SEQ; idx += 128) {
        const int n = idx / SEQ, m = idx % SEQ;
        float acc = 0.f;
#pragma unroll
        for (int c = 0; c < HD; c++)
            acc += qs[n * QSTR + c] * ks[m * QSTR + c];
        sc[idx] = acc * scale + bias_table[rel_index[idx] * NH + h];
    }
    __syncthreads();

    if (tid < SEQ) {
        float mx = -1e30f;
#pragma unroll 7
        for (int m = 0; m < SEQ; m++) mx = fmaxf(mx, sc[tid * SEQ + m]);
        float sum = 0.f;
#pragma unroll 7
        for (int m = 0; m < SEQ; m++) {
            const float e = expf(sc[tid * SEQ + m] - mx);
            sc[tid * SEQ + m] = e;
            sum += e;
        }
        const float inv = 1.f / sum;
#pragma unroll 7
        for (int m = 0; m < SEQ; m++) sc[tid * SEQ + m] *= inv;
    }
    __syncthreads();

    for (int idx = tid; idx < SEQ * HD; idx += 128) {
        const int n = idx / HD, c = idx % HD;
        float acc = 0.f;
#pragma unroll 7
        for (int m = 0; m < SEQ; m++)
            acc += sc[n * SEQ + m] * vs[m * QSTR + c];
        const size_t off = ((size_t)srow[n] * SEQ + n) * EMB + h * HD + c;
        const __nv_bfloat16 hv = __float2bfloat16_rn(acc);
        g_ahi[off] = hv;
        g_alo[off] = __float2bfloat16_rn(acc - __bfloat162float(hv));
    }
}

// ---------------------------------------------------------------------------
extern "C" void kernel_launch(void* const* d_in, const int* in_sizes, int n_in,
                              void* d_out, int out_size)
{
    const float* x          = (const float*)d_in[0];
    const float* qkv_w      = (const float*)d_in[1];
    const float* proj_w     = (const float*)d_in[2];
    const float* proj_b     = (const float*)d_in[3];
    const float* bias_table = (const float*)d_in[4];
    const int*   rel_index  = (const int*)d_in[5];
    float* out = (float*)d_out;

    float* qkvbuf = nullptr;
    __nv_bfloat16 *xhi, *xlo, *ahi, *alo, *w1hi, *w1lo, *w2hi, *w2lo;
    cudaGetSymbolAddress((void**)&qkvbuf, g_qkv);
    cudaGetSymbolAddress((void**)&xhi,  g_xhi);
    cudaGetSymbolAddress((void**)&xlo,  g_xlo);
    cudaGetSymbolAddress((void**)&ahi,  g_ahi);
    cudaGetSymbolAddress((void**)&alo,  g_alo);
    cudaGetSymbolAddress((void**)&w1hi, g_w1hi);
    cudaGetSymbolAddress((void**)&w1lo, g_w1lo);
    cudaGetSymbolAddress((void**)&w2hi, g_w2hi);
    cudaGetSymbolAddress((void**)&w2lo, g_w2lo);

    cudaFuncSetAttribute(gemm_3xbf16<0>, cudaFuncAttributeMaxDynamicSharedMemorySize, GSMEM);
    cudaFuncSetAttribute(gemm_3xbf16<1>, cudaFuncAttributeMaxDynamicSharedMemorySize, GSMEM);

    // Prepass: split inputs to hi/lo bf16
    {
        const int n4x = MROWS * EMB / 4;
        split_kernel<<<(n4x + 255) / 256, 256>>>(x, xhi, xlo, n4x);
        const int n4w1 = QKVN * EMB / 4;
        split_kernel<<<(n4w1 + 255) / 256, 256>>>(qkv_w, w1hi, w1lo, n4w1);
        const int n4w2 = EMB * EMB / 4;
        split_kernel<<<(n4w2 + 255) / 256, 256>>>(proj_w, w2hi, w2lo, n4w2);
    }

    // K1: qkv = x @ qkv_w^T
    {
        dim3 grid(QKVN / 128, MROWS / 128);
        gemm_3xbf16<0><<<grid, 256, GSMEM>>>(xhi, xlo, w1hi, w1lo, nullptr, qkvbuf, QKVN);
    }
    // K2: fused shift + attention + inverse shift (emits hi/lo bf16)
    {
        dim3 grid(BTOT, NH);
        attn_kernel<<<grid, 128>>>(bias_table, rel_index);
    }
    // K3: out = att @ proj_w^T + proj_b
    {
        dim3 grid(EMB / 128, MROWS / 128);
        gemm_3xbf16<1><<<grid, 256, GSMEM>>>(ahi, alo, w2hi, w2lo, proj_b, out, EMB);
    }
}

// round 8
// speedup vs baseline: 2.0277x; 1.0422x over previous
#include <cuda_runtime.h>
#include <cuda_bf16.h>
#include <cstdint>

// Problem constants
#define BTOT   4096
#define SEQ    49
#define EMB    512
#define NH     16
#define HD     32
#define FL     16
#define NWIN   64
#define QKVN   1536
#define MROWS  (BTOT*SEQ)   // 200704

// Scratch (static device globals)
__device__ float         g_qkv[(size_t)MROWS * QKVN];
__device__ __nv_bfloat16 g_xhi[(size_t)MROWS * EMB];
__device__ __nv_bfloat16 g_xlo[(size_t)MROWS * EMB];
__device__ __nv_bfloat16 g_ahi[(size_t)MROWS * EMB];
__device__ __nv_bfloat16 g_alo[(size_t)MROWS * EMB];
__device__ __nv_bfloat16 g_w1hi[QKVN * EMB];
__device__ __nv_bfloat16 g_w1lo[QKVN * EMB];
__device__ __nv_bfloat16 g_w2hi[EMB * EMB];
__device__ __nv_bfloat16 g_w2lo[EMB * EMB];

__constant__ int c_shift[9] = {-4, 1, 2, -1, 0, 3, -2, -3, 4};

// ---------------------------------------------------------------------------
__device__ __forceinline__ uint32_t smem_u32(const void* p) {
    uint32_t a;
    asm("{ .reg .u64 t; cvta.to.shared.u64 t, %1; cvt.u32.u64 %0, t; }" : "=r"(a) : "l"(p));
    return a;
}
__device__ __forceinline__ void cp_async16(uint32_t s, const void* g) {
    asm volatile("cp.async.cg.shared.global [%0], [%1], 16;\n" :: "r"(s), "l"(g));
}
__device__ __forceinline__ void cp_commit() { asm volatile("cp.async.commit_group;\n"); }
__device__ __forceinline__ void cp_wait0()  { asm volatile("cp.async.wait_group 0;\n"); }

__device__ __forceinline__ void mma_bf16(float* d, const uint32_t* a, const uint32_t* b) {
    asm volatile(
        "mma.sync.aligned.m16n8k16.row.col.f32.bf16.bf16.f32 "
        "{%0,%1,%2,%3}, {%4,%5,%6,%7}, {%8,%9}, {%0,%1,%2,%3};\n"
        : "+f"(d[0]), "+f"(d[1]), "+f"(d[2]), "+f"(d[3])
        : "r"(a[0]), "r"(a[1]), "r"(a[2]), "r"(a[3]), "r"(b[0]), "r"(b[1]));
}
__device__ __forceinline__ void ldsm_x4(uint32_t* r, uint32_t addr) {
    asm volatile("ldmatrix.sync.aligned.m8n8.x4.shared.b16 {%0,%1,%2,%3}, [%4];\n"
                 : "=r"(r[0]), "=r"(r[1]), "=r"(r[2]), "=r"(r[3]) : "r"(addr));
}

// ---------------------------------------------------------------------------
// Split fp32 -> (hi, lo) bf16
// ---------------------------------------------------------------------------
__global__ void split_kernel(const float* __restrict__ in,
                             __nv_bfloat16* __restrict__ hi,
                             __nv_bfloat16* __restrict__ lo, int n4)
{
    const int i = blockIdx.x * blockDim.x + threadIdx.x;
    if (i >= n4) return;
    float4 v = reinterpret_cast<const float4*>(in)[i];
    __nv_bfloat16 h0 = __float2bfloat16_rn(v.x);
    __nv_bfloat16 h1 = __float2bfloat16_rn(v.y);
    __nv_bfloat16 h2 = __float2bfloat16_rn(v.z);
    __nv_bfloat16 h3 = __float2bfloat16_rn(v.w);
    __nv_bfloat162* hp = reinterpret_cast<__nv_bfloat162*>(hi);
    __nv_bfloat162* lp = reinterpret_cast<__nv_bfloat162*>(lo);
    hp[2 * i]     = __nv_bfloat162(h0, h1);
    hp[2 * i + 1] = __nv_bfloat162(h2, h3);
    lp[2 * i]     = __nv_bfloat162(__float2bfloat16_rn(v.x - __bfloat162float(h0)),
                                   __float2bfloat16_rn(v.y - __bfloat162float(h1)));
    lp[2 * i + 1] = __nv_bfloat162(__float2bfloat16_rn(v.z - __bfloat162float(h2)),
                                   __float2bfloat16_rn(v.w - __bfloat162float(h3)));
}

// ---------------------------------------------------------------------------
// 3xBF16 tensor-core GEMM (NT). 128x128 CTA tile, 4 warps (2x2), warp tile
// 64x64, BK=32, m16n8k16 mma. 80B smem row stride, cp.async double buffer.
// 2 CTAs/SM. Warp tile 64x64 halves ldsm traffic per FLOP vs 32x64.
// ---------------------------------------------------------------------------
#define BK     32
#define RSTR   80
#define TILEB  (128 * RSTR)
#define BUFB   (4 * TILEB)
#define GSMEM  (2 * BUFB)   // 81920

template <int WITH_BIAS>
__global__ __launch_bounds__(128, 2) void gemm_3xbf16(
    const __nv_bfloat16* __restrict__ Ahi, const __nv_bfloat16* __restrict__ Alo,
    const __nv_bfloat16* __restrict__ Bhi, const __nv_bfloat16* __restrict__ Blo,
    const float* __restrict__ bias, float* __restrict__ C, int N)
{
    extern __shared__ unsigned char dsmem[];
    const uint32_t sbase = smem_u32(dsmem);

    const int tid    = threadIdx.x;
    const int lane   = tid & 31;
    const int wid    = tid >> 5;
    const int warp_m = wid >> 1;   // 0..1
    const int warp_n = wid & 1;    // 0..1
    const int bm = blockIdx.y * 128;
    const int bn = blockIdx.x * 128;

    // cp.async: each thread owns one row (64B = 4 segs of 16B) per tile
    const __nv_bfloat16* gAh = Ahi + (size_t)(bm + tid) * EMB;
    const __nv_bfloat16* gAl = Alo + (size_t)(bm + tid) * EMB;
    const __nv_bfloat16* gBh = Bhi + (size_t)(bn + tid) * EMB;
    const __nv_bfloat16* gBl = Blo + (size_t)(bn + tid) * EMB;

    auto load_chunk = [&](int ch, int buf) {
        const uint32_t dst = sbase + buf * BUFB + tid * RSTR;
        const int gb = ch * (BK * 2);
#pragma unroll
        for (int s = 0; s < 4; s++) {
            const int sb = s * 16;
            cp_async16(dst + sb,             (const char*)gAh + gb + sb);
            cp_async16(dst + TILEB + sb,     (const char*)gAl + gb + sb);
            cp_async16(dst + 2 * TILEB + sb, (const char*)gBh + gb + sb);
            cp_async16(dst + 3 * TILEB + sb, (const char*)gBl + gb + sb);
        }
    };

    const uint32_t a_off = (uint32_t)((warp_m * 64 + (lane & 15)) * RSTR + (lane >> 4) * 16);
    const uint32_t b_off = (uint32_t)((warp_n * 64 + (lane & 7) + ((lane >> 4) << 3)) * RSTR
                                      + ((lane >> 3) & 1) * 16);

    float acc[4][8][4];
#pragma unroll
    for (int mt = 0; mt < 4; mt++)
#pragma unroll
        for (int nt = 0; nt < 8; nt++)
#pragma unroll
            for (int r = 0; r < 4; r++) acc[mt][nt][r] = 0.f;

    const int nchunk = EMB / BK;   // 16
    load_chunk(0, 0);
    cp_commit();

    for (int i = 0; i < nchunk; i++) {
        cp_wait0();
        __syncthreads();
        if (i + 1 < nchunk) { load_chunk(i + 1, (i + 1) & 1); cp_commit(); }

        const uint32_t base = sbase + (i & 1) * BUFB;

#pragma unroll
        for (int kk = 0; kk < 2; kk++) {
            const uint32_t kb = kk * 32;
            uint32_t ah[4][4], al[4][4];
#pragma unroll
            for (int mt = 0; mt < 4; mt++) {
                ldsm_x4(ah[mt], base + a_off + mt * (16 * RSTR) + kb);
                ldsm_x4(al[mt], base + TILEB + a_off + mt * (16 * RSTR) + kb);
            }
#pragma unroll
            for (int ng = 0; ng < 4; ng++) {
                uint32_t bh[4], bl[4];
                ldsm_x4(bh, base + 2 * TILEB + b_off + ng * (16 * RSTR) + kb);
                ldsm_x4(bl, base + 3 * TILEB + b_off + ng * (16 * RSTR) + kb);
#pragma unroll
                for (int j = 0; j < 2; j++) {
                    const int nt = 2 * ng + j;
#pragma unroll
                    for (int mt = 0; mt < 4; mt++) {
                        mma_bf16(acc[mt][nt], ah[mt], bh + 2 * j);
                        mma_bf16(acc[mt][nt], al[mt], bh + 2 * j);
                        mma_bf16(acc[mt][nt], ah[mt], bl + 2 * j);
                    }
                }
            }
        }
        __syncthreads();
    }

    const int lr  = lane >> 2;
    const int lc2 = (lane & 3) * 2;
#pragma unroll
    for (int mt = 0; mt < 4; mt++) {
        const int row0 = bm + warp_m * 64 + mt * 16 + lr;
#pragma unroll
        for (int nt = 0; nt < 8; nt++) {
            const int col = bn + warp_n * 64 + nt * 8 + lc2;
            float2 v0 = make_float2(acc[mt][nt][0], acc[mt][nt][1]);
            float2 v1 = make_float2(acc[mt][nt][2], acc[mt][nt][3]);
            if (WITH_BIAS) {
                v0.x += bias[col]; v0.y += bias[col + 1];
                v1.x += bias[col]; v1.y += bias[col + 1];
            }
            *reinterpret_cast<float2*>(C + (size_t)row0 * N + col)       = v0;
            *reinterpret_cast<float2*>(C + (size_t)(row0 + 8) * N + col) = v1;
        }
    }
}

// ---------------------------------------------------------------------------
// Fused shift-gather + attention + inverse-shift scatter.
// Scores: K columns register-resident (thread-per-m), Q warp-broadcast.
// PV: V sub-columns register-resident, partial sums in smem.
// Emits hi/lo bf16 for the K3 GEMM.
// ---------------------------------------------------------------------------
#define AST 36   // floats per smem row (16B aligned, 32 data + 4 pad)

__global__ __launch_bounds__(128) void attn_kernel(
    const float* __restrict__ bias_table,
    const int*   __restrict__ rel_index)
{
    const int b   = blockIdx.x;
    const int h   = blockIdx.y;
    const int tid = threadIdx.x;

    __shared__ float qs[SEQ * AST];
    __shared__ float ks[SEQ * AST];
    __shared__ float vs[SEQ * AST];
    __shared__ float sc[SEQ * SEQ];
    __shared__ float part[2 * SEQ * HD];   // [mq][n][c]
    __shared__ int   srow[SEQ];

    const int t = (b / NWIN) % FL;

    if (tid < SEQ) {
        const int i = tid / 7, j = tid % 7;
        const int s = c_shift[(i % 3) * 3 + (j % 3)];
        const int tsrc = (t - s + 2 * FL) % FL;
        srow[tid] = b + (tsrc - t) * NWIN;
    }
    __syncthreads();

    // gather q/k/v rows (float4)
    for (int idx = tid; idx < SEQ * 8; idx += 128) {
        const int n = idx >> 3, f = idx & 7;
        const size_t base = ((size_t)srow[n] * SEQ + n) * QKVN + h * HD + f * 4;
        const int sm = n * AST + f * 4;
        *reinterpret_cast<float4*>(&qs[sm]) = *reinterpret_cast<const float4*>(&g_qkv[base]);
        *reinterpret_cast<float4*>(&ks[sm]) = *reinterpret_cast<const float4*>(&g_qkv[base + EMB]);
        *reinterpret_cast<float4*>(&vs[sm]) = *reinterpret_cast<const float4*>(&g_qkv[base + 2 * EMB]);
    }
    __syncthreads();

    const float scale = 0.1767766952966369f;

    // scores: threads 0..97: m = tid%49, n-half = tid/49; K col in registers
    if (tid < 98) {
        const int m  = (tid < SEQ) ? tid : tid - SEQ;
        const int n0 = (tid < SEQ) ? 0 : 25;
        const int n1 = (tid < SEQ) ? 25 : SEQ;
        float kr[HD];
#pragma unroll
        for (int f = 0; f < 8; f++)
            *reinterpret_cast<float4*>(&kr[f * 4]) = *reinterpret_cast<const float4*>(&ks[m * AST + f * 4]);
        for (int n = n0; n < n1; n++) {
            float acc = 0.f;
#pragma unroll
            for (int f = 0; f < 8; f++) {
                float4 q4 = *reinterpret_cast<const float4*>(&qs[n * AST + f * 4]);
                acc += q4.x * kr[f * 4] + q4.y * kr[f * 4 + 1]
                     + q4.z * kr[f * 4 + 2] + q4.w * kr[f * 4 + 3];
            }
            sc[n * SEQ + m] = acc * scale + bias_table[rel_index[n * SEQ + m] * NH + h];
        }
    }
    __syncthreads();

    // softmax per row
    if (tid < SEQ) {
        float mx = -1e30f;
#pragma unroll 7
        for (int m = 0; m < SEQ; m++) mx = fmaxf(mx, sc[tid * SEQ + m]);
        float sum = 0.f;
#pragma unroll 7
        for (int m = 0; m < SEQ; m++) {
            const float e = __expf(sc[tid * SEQ + m] - mx);
            sc[tid * SEQ + m] = e;
            sum += e;
        }
        const float inv = 1.f / sum;
#pragma unroll 7
        for (int m = 0; m < SEQ; m++) sc[tid * SEQ + m] *= inv;
    }
    __syncthreads();

    // PV: thread = (mq, nh, c); V sub-column in registers
    {
        const int c  = tid & 31;
        const int nh = (tid >> 5) & 1;
        const int mq = (tid >> 6) & 1;
        const int mb = mq * 25;
        const int mc = mq ? 24 : 25;
        const int n0 = nh * 25;
        const int n1 = nh ? SEQ : 25;
        float vr[25];
        for (int i = 0; i < mc; i++) vr[i] = vs[(mb + i) * AST + c];
        for (int n = n0; n < n1; n++) {
            float a = 0.f;
            for (int i = 0; i < mc; i++) a += sc[n * SEQ + mb + i] * vr[i];
            part[(mq * SEQ + n) * HD + c] = a;
        }
    }
    __syncthreads();

    // reduce partials, split hi/lo, scatter (same rows as gather)
    for (int idx = tid; idx < SEQ * (HD / 2); idx += 128) {
        const int n = idx / (HD / 2);
        const int c = (idx % (HD / 2)) * 2;
        const float s0 = part[n * HD + c]     + part[(SEQ + n) * HD + c];
        const float s1 = part[n * HD + c + 1] + part[(SEQ + n) * HD + c + 1];
        const size_t off = ((size_t)srow[n] * SEQ + n) * EMB + h * HD + c;
        const __nv_bfloat16 h0 = __float2bfloat16_rn(s0);
        const __nv_bfloat16 h1 = __float2bfloat16_rn(s1);
        *reinterpret_cast<__nv_bfloat162*>(&g_ahi[off]) = __nv_bfloat162(h0, h1);
        *reinterpret_cast<__nv_bfloat162*>(&g_alo[off]) =
            __nv_bfloat162(__float2bfloat16_rn(s0 - __bfloat162float(h0)),
                           __float2bfloat16_rn(s1 - __bfloat162float(h1)));
    }
}

// ---------------------------------------------------------------------------
extern "C" void kernel_launch(void* const* d_in, const int* in_sizes, int n_in,
                              void* d_out, int out_size)
{
    const float* x          = (const float*)d_in[0];
    const float* qkv_w      = (const float*)d_in[1];
    const float* proj_w     = (const float*)d_in[2];
    const float* proj_b     = (const float*)d_in[3];
    const float* bias_table = (const float*)d_in[4];
    const int*   rel_index  = (const int*)d_in[5];
    float* out = (float*)d_out;

    float* qkvbuf = nullptr;
    __nv_bfloat16 *xhi, *xlo, *ahi, *alo, *w1hi, *w1lo, *w2hi, *w2lo;
    cudaGetSymbolAddress((void**)&qkvbuf, g_qkv);
    cudaGetSymbolAddress((void**)&xhi,  g_xhi);
    cudaGetSymbolAddress((void**)&xlo,  g_xlo);
    cudaGetSymbolAddress((void**)&ahi,  g_ahi);
    cudaGetSymbolAddress((void**)&alo,  g_alo);
    cudaGetSymbolAddress((void**)&w1hi, g_w1hi);
    cudaGetSymbolAddress((void**)&w1lo, g_w1lo);
    cudaGetSymbolAddress((void**)&w2hi, g_w2hi);
    cudaGetSymbolAddress((void**)&w2lo, g_w2lo);

    cudaFuncSetAttribute(gemm_3xbf16<0>, cudaFuncAttributeMaxDynamicSharedMemorySize, GSMEM);
    cudaFuncSetAttribute(gemm_3xbf16<1>, cudaFuncAttributeMaxDynamicSharedMemorySize, GSMEM);

    // Prepass: split inputs to hi/lo bf16
    {
        const int n4x = MROWS * EMB / 4;
        split_kernel<<<(n4x + 255) / 256, 256>>>(x, xhi, xlo, n4x);
        const int n4w1 = QKVN * EMB / 4;
        split_kernel<<<(n4w1 + 255) / 256, 256>>>(qkv_w, w1hi, w1lo, n4w1);
        const int n4w2 = EMB * EMB / 4;
        split_kernel<<<(n4w2 + 255) / 256, 256>>>(proj_w, w2hi, w2lo, n4w2);
    }

    // K1: qkv = x @ qkv_w^T
    {
        dim3 grid(QKVN / 128, MROWS / 128);
        gemm_3xbf16<0><<<grid, 128, GSMEM>>>(xhi, xlo, w1hi, w1lo, nullptr, qkvbuf, QKVN);
    }
    // K2: fused shift + attention + inverse shift (emits hi/lo bf16)
    {
        dim3 grid(BTOT, NH);
        attn_kernel<<<grid, 128>>>(bias_table, rel_index);
    }
    // K3: out = att @ proj_w^T + proj_b
    {
        dim3 grid(EMB / 128, MROWS / 128);
        gemm_3xbf16<1><<<grid, 128, GSMEM>>>(ahi, alo, w2hi, w2lo, proj_b, out, EMB);
    }
}

// round 9
// speedup vs baseline: 2.3866x; 1.1770x over previous
#include <cuda_runtime.h>
#include <cuda_bf16.h>
#include <cstdint>

// Problem constants
#define BTOT   4096
#define SEQ    49
#define EMB    512
#define NH     16
#define HD     32
#define FL     16
#define NWIN   64
#define QKVN   1536
#define MROWS  (BTOT*SEQ)   // 200704

// Scratch (static device globals)
__device__ float         g_qkv[(size_t)MROWS * QKVN];
__device__ __nv_bfloat16 g_xhi[(size_t)MROWS * EMB];
__device__ __nv_bfloat16 g_xlo[(size_t)MROWS * EMB];
__device__ __nv_bfloat16 g_ahi[(size_t)MROWS * EMB];
__device__ __nv_bfloat16 g_alo[(size_t)MROWS * EMB];
__device__ __nv_bfloat16 g_w1hi[QKVN * EMB];
__device__ __nv_bfloat16 g_w1lo[QKVN * EMB];
__device__ __nv_bfloat16 g_w2hi[EMB * EMB];
__device__ __nv_bfloat16 g_w2lo[EMB * EMB];

__constant__ int c_shift[9] = {-4, 1, 2, -1, 0, 3, -2, -3, 4};

// ---------------------------------------------------------------------------
__device__ __forceinline__ uint32_t smem_u32(const void* p) {
    uint32_t a;
    asm("{ .reg .u64 t; cvta.to.shared.u64 t, %1; cvt.u32.u64 %0, t; }" : "=r"(a) : "l"(p));
    return a;
}
__device__ __forceinline__ void cp_async16(uint32_t s, const void* g) {
    asm volatile("cp.async.cg.shared.global [%0], [%1], 16;\n" :: "r"(s), "l"(g));
}
__device__ __forceinline__ void cp_commit() { asm volatile("cp.async.commit_group;\n"); }
__device__ __forceinline__ void cp_wait0()  { asm volatile("cp.async.wait_group 0;\n"); }

__device__ __forceinline__ void mma_bf16(float* d, const uint32_t* a, const uint32_t* b) {
    asm volatile(
        "mma.sync.aligned.m16n8k16.row.col.f32.bf16.bf16.f32 "
        "{%0,%1,%2,%3}, {%4,%5,%6,%7}, {%8,%9}, {%0,%1,%2,%3};\n"
        : "+f"(d[0]), "+f"(d[1]), "+f"(d[2]), "+f"(d[3])
        : "r"(a[0]), "r"(a[1]), "r"(a[2]), "r"(a[3]), "r"(b[0]), "r"(b[1]));
}
__device__ __forceinline__ void ldsm_x4(uint32_t* r, uint32_t addr) {
    asm volatile("ldmatrix.sync.aligned.m8n8.x4.shared.b16 {%0,%1,%2,%3}, [%4];\n"
                 : "=r"(r[0]), "=r"(r[1]), "=r"(r[2]), "=r"(r[3]) : "r"(addr));
}

// ---------------------------------------------------------------------------
// Split fp32 -> (hi, lo) bf16
// ---------------------------------------------------------------------------
__global__ void split_kernel(const float* __restrict__ in,
                             __nv_bfloat16* __restrict__ hi,
                             __nv_bfloat16* __restrict__ lo, int n4)
{
    const int i = blockIdx.x * blockDim.x + threadIdx.x;
    if (i >= n4) return;
    float4 v = reinterpret_cast<const float4*>(in)[i];
    __nv_bfloat16 h0 = __float2bfloat16_rn(v.x);
    __nv_bfloat16 h1 = __float2bfloat16_rn(v.y);
    __nv_bfloat16 h2 = __float2bfloat16_rn(v.z);
    __nv_bfloat16 h3 = __float2bfloat16_rn(v.w);
    __nv_bfloat162* hp = reinterpret_cast<__nv_bfloat162*>(hi);
    __nv_bfloat162* lp = reinterpret_cast<__nv_bfloat162*>(lo);
    hp[2 * i]     = __nv_bfloat162(h0, h1);
    hp[2 * i + 1] = __nv_bfloat162(h2, h3);
    lp[2 * i]     = __nv_bfloat162(__float2bfloat16_rn(v.x - __bfloat162float(h0)),
                                   __float2bfloat16_rn(v.y - __bfloat162float(h1)));
    lp[2 * i + 1] = __nv_bfloat162(__float2bfloat16_rn(v.z - __bfloat162float(h2)),
                                   __float2bfloat16_rn(v.w - __bfloat162float(h3)));
}

// ---------------------------------------------------------------------------
// 3xBF16 tensor-core GEMM (NT) — R5 configuration (measured best: tensor 58%).
// 128x128 CTA tile, BK=32, 8 warps (4x2), warp tile 32x64, m16n8k16 mma.
// 80B smem row stride (conflict-free ldmatrix), cp.async double buffer,
// 2 CTAs/SM (reg cap 128).
// ---------------------------------------------------------------------------
#define BK     32
#define RSTR   80
#define TILEB  (128 * RSTR)
#define BUFB   (4 * TILEB)
#define GSMEM  (2 * BUFB)   // 81920

template <int WITH_BIAS>
__global__ __launch_bounds__(256, 2) void gemm_3xbf16(
    const __nv_bfloat16* __restrict__ Ahi, const __nv_bfloat16* __restrict__ Alo,
    const __nv_bfloat16* __restrict__ Bhi, const __nv_bfloat16* __restrict__ Blo,
    const float* __restrict__ bias, float* __restrict__ C, int N)
{
    extern __shared__ unsigned char dsmem[];
    const uint32_t sbase = smem_u32(dsmem);

    const int tid    = threadIdx.x;
    const int lane   = tid & 31;
    const int wid    = tid >> 5;
    const int warp_m = wid >> 1;       // 0..3
    const int warp_n = wid & 1;        // 0..1
    const int bm = blockIdx.y * 128;
    const int bn = blockIdx.x * 128;

    // cp.async mapping: row = tid>>1 (0..127), 2 segs of 16B per tile
    const int lrow = tid >> 1;
    const int seg0 = (tid & 1) * 2;
    const __nv_bfloat16* gAh = Ahi + (size_t)(bm + lrow) * EMB;
    const __nv_bfloat16* gAl = Alo + (size_t)(bm + lrow) * EMB;
    const __nv_bfloat16* gBh = Bhi + (size_t)(bn + lrow) * EMB;
    const __nv_bfloat16* gBl = Blo + (size_t)(bn + lrow) * EMB;

    auto load_chunk = [&](int ch, int buf) {
        const uint32_t dst = sbase + buf * BUFB + lrow * RSTR;
        const int gb = ch * (BK * 2);
#pragma unroll
        for (int s = 0; s < 2; s++) {
            const int sb = (seg0 + s) * 16;
            cp_async16(dst + sb,             (const char*)gAh + gb + sb);
            cp_async16(dst + TILEB + sb,     (const char*)gAl + gb + sb);
            cp_async16(dst + 2 * TILEB + sb, (const char*)gBh + gb + sb);
            cp_async16(dst + 3 * TILEB + sb, (const char*)gBl + gb + sb);
        }
    };

    const uint32_t a_off = (uint32_t)((warp_m * 32 + (lane & 15)) * RSTR + (lane >> 4) * 16);
    const uint32_t b_off = (uint32_t)((warp_n * 64 + (lane & 7) + ((lane >> 4) << 3)) * RSTR
                                      + ((lane >> 3) & 1) * 16);

    float acc[2][8][4];
#pragma unroll
    for (int mt = 0; mt < 2; mt++)
#pragma unroll
        for (int nt = 0; nt < 8; nt++)
#pragma unroll
            for (int r = 0; r < 4; r++) acc[mt][nt][r] = 0.f;

    const int nchunk = EMB / BK;   // 16
    load_chunk(0, 0);
    cp_commit();

    for (int i = 0; i < nchunk; i++) {
        cp_wait0();
        __syncthreads();
        if (i + 1 < nchunk) { load_chunk(i + 1, (i + 1) & 1); cp_commit(); }

        const uint32_t base = sbase + (i & 1) * BUFB;

#pragma unroll
        for (int kk = 0; kk < 2; kk++) {
            const uint32_t kb = kk * 32;
            uint32_t ah[2][4], al[2][4];
#pragma unroll
            for (int mt = 0; mt < 2; mt++) {
                ldsm_x4(ah[mt], base + a_off + mt * (16 * RSTR) + kb);
                ldsm_x4(al[mt], base + TILEB + a_off + mt * (16 * RSTR) + kb);
            }
#pragma unroll
            for (int ng = 0; ng < 4; ng++) {
                uint32_t bh[4], bl[4];
                ldsm_x4(bh, base + 2 * TILEB + b_off + ng * (16 * RSTR) + kb);
                ldsm_x4(bl, base + 3 * TILEB + b_off + ng * (16 * RSTR) + kb);
#pragma unroll
                for (int j = 0; j < 2; j++) {
                    const int nt = 2 * ng + j;
#pragma unroll
                    for (int mt = 0; mt < 2; mt++) {
                        mma_bf16(acc[mt][nt], ah[mt], bh + 2 * j);
                        mma_bf16(acc[mt][nt], al[mt], bh + 2 * j);
                        mma_bf16(acc[mt][nt], ah[mt], bl + 2 * j);
                    }
                }
            }
        }
        __syncthreads();
    }

    const int lr  = lane >> 2;
    const int lc2 = (lane & 3) * 2;
#pragma unroll
    for (int mt = 0; mt < 2; mt++) {
        const int row0 = bm + warp_m * 32 + mt * 16 + lr;
#pragma unroll
        for (int nt = 0; nt < 8; nt++) {
            const int col = bn + warp_n * 64 + nt * 8 + lc2;
            float2 v0 = make_float2(acc[mt][nt][0], acc[mt][nt][1]);
            float2 v1 = make_float2(acc[mt][nt][2], acc[mt][nt][3]);
            if (WITH_BIAS) {
                v0.x += bias[col]; v0.y += bias[col + 1];
                v1.x += bias[col]; v1.y += bias[col + 1];
            }
            *reinterpret_cast<float2*>(C + (size_t)row0 * N + col)       = v0;
            *reinterpret_cast<float2*>(C + (size_t)(row0 + 8) * N + col) = v1;
        }
    }
}

// ---------------------------------------------------------------------------
// Fused shift-gather + attention + inverse-shift scatter (R6 version).
// Scores: K columns register-resident; PV: V sub-columns register-resident.
// Emits hi/lo bf16 for the K3 GEMM.
// ---------------------------------------------------------------------------
#define AST 36

__global__ __launch_bounds__(128) void attn_kernel(
    const float* __restrict__ bias_table,
    const int*   __restrict__ rel_index)
{
    const int b   = blockIdx.x;
    const int h   = blockIdx.y;
    const int tid = threadIdx.x;

    __shared__ float qs[SEQ * AST];
    __shared__ float ks[SEQ * AST];
    __shared__ float vs[SEQ * AST];
    __shared__ float sc[SEQ * SEQ];
    __shared__ float part[2 * SEQ * HD];
    __shared__ int   srow[SEQ];

    const int t = (b / NWIN) % FL;

    if (tid < SEQ) {
        const int i = tid / 7, j = tid % 7;
        const int s = c_shift[(i % 3) * 3 + (j % 3)];
        const int tsrc = (t - s + 2 * FL) % FL;
        srow[tid] = b + (tsrc - t) * NWIN;
    }
    __syncthreads();

    for (int idx = tid; idx < SEQ * 8; idx += 128) {
        const int n = idx >> 3, f = idx & 7;
        const size_t base = ((size_t)srow[n] * SEQ + n) * QKVN + h * HD + f * 4;
        const int sm = n * AST + f * 4;
        *reinterpret_cast<float4*>(&qs[sm]) = *reinterpret_cast<const float4*>(&g_qkv[base]);
        *reinterpret_cast<float4*>(&ks[sm]) = *reinterpret_cast<const float4*>(&g_qkv[base + EMB]);
        *reinterpret_cast<float4*>(&vs[sm]) = *reinterpret_cast<const float4*>(&g_qkv[base + 2 * EMB]);
    }
    __syncthreads();

    const float scale = 0.1767766952966369f;

    if (tid < 98) {
        const int m  = (tid < SEQ) ? tid : tid - SEQ;
        const int n0 = (tid < SEQ) ? 0 : 25;
        const int n1 = (tid < SEQ) ? 25 : SEQ;
        float kr[HD];
#pragma unroll
        for (int f = 0; f < 8; f++)
            *reinterpret_cast<float4*>(&kr[f * 4]) = *reinterpret_cast<const float4*>(&ks[m * AST + f * 4]);
        for (int n = n0; n < n1; n++) {
            float acc = 0.f;
#pragma unroll
            for (int f = 0; f < 8; f++) {
                float4 q4 = *reinterpret_cast<const float4*>(&qs[n * AST + f * 4]);
                acc += q4.x * kr[f * 4] + q4.y * kr[f * 4 + 1]
                     + q4.z * kr[f * 4 + 2] + q4.w * kr[f * 4 + 3];
            }
            sc[n * SEQ + m] = acc * scale + bias_table[rel_index[n * SEQ + m] * NH + h];
        }
    }
    __syncthreads();

    if (tid < SEQ) {
        float mx = -1e30f;
#pragma unroll 7
        for (int m = 0; m < SEQ; m++) mx = fmaxf(mx, sc[tid * SEQ + m]);
        float sum = 0.f;
#pragma unroll 7
        for (int m = 0; m < SEQ; m++) {
            const float e = __expf(sc[tid * SEQ + m] - mx);
            sc[tid * SEQ + m] = e;
            sum += e;
        }
        const float inv = 1.f / sum;
#pragma unroll 7
        for (int m = 0; m < SEQ; m++) sc[tid * SEQ + m] *= inv;
    }
    __syncthreads();

    {
        const int c  = tid & 31;
        const int nh = (tid >> 5) & 1;
        const int mq = (tid >> 6) & 1;
        const int mb = mq * 25;
        const int mc = mq ? 24 : 25;
        const int n0 = nh * 25;
        const int n1 = nh ? SEQ : 25;
        float vr[25];
        for (int i = 0; i < mc; i++) vr[i] = vs[(mb + i) * AST + c];
        for (int n = n0; n < n1; n++) {
            float a = 0.f;
            for (int i = 0; i < mc; i++) a += sc[n * SEQ + mb + i] * vr[i];
            part[(mq * SEQ + n) * HD + c] = a;
        }
    }
    __syncthreads();

    for (int idx = tid; idx < SEQ * (HD / 2); idx += 128) {
        const int n = idx / (HD / 2);
        const int c = (idx % (HD / 2)) * 2;
        const float s0 = part[n * HD + c]     + part[(SEQ + n) * HD + c];
        const float s1 = part[n * HD + c + 1] + part[(SEQ + n) * HD + c + 1];
        const size_t off = ((size_t)srow[n] * SEQ + n) * EMB + h * HD + c;
        const __nv_bfloat16 h0 = __float2bfloat16_rn(s0);
        const __nv_bfloat16 h1 = __float2bfloat16_rn(s1);
        *reinterpret_cast<__nv_bfloat162*>(&g_ahi[off]) = __nv_bfloat162(h0, h1);
        *reinterpret_cast<__nv_bfloat162*>(&g_alo[off]) =
            __nv_bfloat162(__float2bfloat16_rn(s0 - __bfloat162float(h0)),
                           __float2bfloat16_rn(s1 - __bfloat162float(h1)));
    }
}

// ---------------------------------------------------------------------------
extern "C" void kernel_launch(void* const* d_in, const int* in_sizes, int n_in,
                              void* d_out, int out_size)
{
    const float* x          = (const float*)d_in[0];
    const float* qkv_w      = (const float*)d_in[1];
    const float* proj_w     = (const float*)d_in[2];
    const float* proj_b     = (const float*)d_in[3];
    const float* bias_table = (const float*)d_in[4];
    const int*   rel_index  = (const int*)d_in[5];
    float* out = (float*)d_out;

    float* qkvbuf = nullptr;
    __nv_bfloat16 *xhi, *xlo, *ahi, *alo, *w1hi, *w1lo, *w2hi, *w2lo;
    cudaGetSymbolAddress((void**)&qkvbuf, g_qkv);
    cudaGetSymbolAddress((void**)&xhi,  g_xhi);
    cudaGetSymbolAddress((void**)&xlo,  g_xlo);
    cudaGetSymbolAddress((void**)&ahi,  g_ahi);
    cudaGetSymbolAddress((void**)&alo,  g_alo);
    cudaGetSymbolAddress((void**)&w1hi, g_w1hi);
    cudaGetSymbolAddress((void**)&w1lo, g_w1lo);
    cudaGetSymbolAddress((void**)&w2hi, g_w2hi);
    cudaGetSymbolAddress((void**)&w2lo, g_w2lo);

    cudaFuncSetAttribute(gemm_3xbf16<0>, cudaFuncAttributeMaxDynamicSharedMemorySize, GSMEM);
    cudaFuncSetAttribute(gemm_3xbf16<1>, cudaFuncAttributeMaxDynamicSharedMemorySize, GSMEM);

    // Prepass: split inputs to hi/lo bf16
    {
        const int n4x = MROWS * EMB / 4;
        split_kernel<<<(n4x + 255) / 256, 256>>>(x, xhi, xlo, n4x);
        const int n4w1 = QKVN * EMB / 4;
        split_kernel<<<(n4w1 + 255) / 256, 256>>>(qkv_w, w1hi, w1lo, n4w1);
        const int n4w2 = EMB * EMB / 4;
        split_kernel<<<(n4w2 + 255) / 256, 256>>>(proj_w, w2hi, w2lo, n4w2);
    }

    // K1: qkv = x @ qkv_w^T
    {
        dim3 grid(QKVN / 128, MROWS / 128);
        gemm_3xbf16<0><<<grid, 256, GSMEM>>>(xhi, xlo, w1hi, w1lo, nullptr, qkvbuf, QKVN);
    }
    // K2: fused shift + attention + inverse shift (emits hi/lo bf16)
    {
        dim3 grid(BTOT, NH);
        attn_kernel<<<grid, 128>>>(bias_table, rel_index);
    }
    // K3: out = att @ proj_w^T + proj_b
    {
        dim3 grid(EMB / 128, MROWS / 128);
        gemm_3xbf16<1><<<grid, 256, GSMEM>>>(ahi, alo, w2hi, w2lo, proj_b, out, EMB);
    }
}

// round 11
// speedup vs baseline: 2.6423x; 1.1072x over previous
#include <cuda_runtime.h>
#include <cuda_bf16.h>
#include <cstdint>

// Problem constants
#define BTOT   4096
#define SEQ    49
#define EMB    512
#define NH     16
#define HD     32
#define FL     16
#define NWIN   64
#define QKVN   1536
#define MROWS  (BTOT*SEQ)   // 200704

// Scratch (static device globals)
__device__ float         g_qkv[(size_t)MROWS * QKVN];
__device__ __nv_bfloat16 g_xhi[(size_t)MROWS * EMB];
__device__ __nv_bfloat16 g_xlo[(size_t)MROWS * EMB];
__device__ __nv_bfloat16 g_ahi[(size_t)MROWS * EMB];
__device__ __nv_bfloat16 g_alo[(size_t)MROWS * EMB];
__device__ __nv_bfloat16 g_w1hi[QKVN * EMB];
__device__ __nv_bfloat16 g_w1lo[QKVN * EMB];
__device__ __nv_bfloat16 g_w2hi[EMB * EMB];
__device__ __nv_bfloat16 g_w2lo[EMB * EMB];

__constant__ int c_shift[9] = {-4, 1, 2, -1, 0, 3, -2, -3, 4};

// ---------------------------------------------------------------------------
__device__ __forceinline__ uint32_t smem_u32(const void* p) {
    uint32_t a;
    asm("{ .reg .u64 t; cvta.to.shared.u64 t, %1; cvt.u32.u64 %0, t; }" : "=r"(a) : "l"(p));
    return a;
}
__device__ __forceinline__ void cp_async16(uint32_t s, const void* g) {
    asm volatile("cp.async.cg.shared.global [%0], [%1], 16;\n" :: "r"(s), "l"(g));
}
__device__ __forceinline__ void cp_commit() { asm volatile("cp.async.commit_group;\n"); }
__device__ __forceinline__ void cp_wait1()  { asm volatile("cp.async.wait_group 1;\n"); }

__device__ __forceinline__ void mma_bf16(float* d, const uint32_t* a, const uint32_t* b) {
    asm volatile(
        "mma.sync.aligned.m16n8k16.row.col.f32.bf16.bf16.f32 "
        "{%0,%1,%2,%3}, {%4,%5,%6,%7}, {%8,%9}, {%0,%1,%2,%3};\n"
        : "+f"(d[0]), "+f"(d[1]), "+f"(d[2]), "+f"(d[3])
        : "r"(a[0]), "r"(a[1]), "r"(a[2]), "r"(a[3]), "r"(b[0]), "r"(b[1]));
}
__device__ __forceinline__ void ldsm_x4(uint32_t* r, uint32_t addr) {
    asm volatile("ldmatrix.sync.aligned.m8n8.x4.shared.b16 {%0,%1,%2,%3}, [%4];\n"
                 : "=r"(r[0]), "=r"(r[1]), "=r"(r[2]), "=r"(r[3]) : "r"(addr));
}

// ---------------------------------------------------------------------------
// Split fp32 -> (hi, lo) bf16
// ---------------------------------------------------------------------------
__global__ void split_kernel(const float* __restrict__ in,
                             __nv_bfloat16* __restrict__ hi,
                             __nv_bfloat16* __restrict__ lo, int n4)
{
    const int i = blockIdx.x * blockDim.x + threadIdx.x;
    if (i >= n4) return;
    float4 v = reinterpret_cast<const float4*>(in)[i];
    __nv_bfloat16 h0 = __float2bfloat16_rn(v.x);
    __nv_bfloat16 h1 = __float2bfloat16_rn(v.y);
    __nv_bfloat16 h2 = __float2bfloat16_rn(v.z);
    __nv_bfloat16 h3 = __float2bfloat16_rn(v.w);
    __nv_bfloat162* hp = reinterpret_cast<__nv_bfloat162*>(hi);
    __nv_bfloat162* lp = reinterpret_cast<__nv_bfloat162*>(lo);
    hp[2 * i]     = __nv_bfloat162(h0, h1);
    hp[2 * i + 1] = __nv_bfloat162(h2, h3);
    lp[2 * i]     = __nv_bfloat162(__float2bfloat16_rn(v.x - __bfloat162float(h0)),
                                   __float2bfloat16_rn(v.y - __bfloat162float(h1)));
    lp[2 * i + 1] = __nv_bfloat162(__float2bfloat16_rn(v.z - __bfloat162float(h2)),
                                   __float2bfloat16_rn(v.w - __bfloat162float(h3)));
}

// ---------------------------------------------------------------------------
// 3xBF16 tensor-core GEMM (NT). 128x128 CTA tile, BK=32, 8 warps (4x2),
// warp tile 32x64, m16n8k16 mma. XOR-swizzled 64B smem rows (no pad):
// chunk ^= (row>>1)&3 makes each 8-row ldmatrix group span all 32 banks.
// Tile = 8KB; 3-stage cp.async pipeline (prefetch depth 2); 2 CTAs/SM.
// ---------------------------------------------------------------------------
#define BK     32
#define TILEB  (128 * 64)          // 8192 B per tile
#define BUFB   (4 * TILEB)         // Ahi, Alo, Bhi, Blo = 32768 B
#define NSTAGE 3
#define GSMEM  (NSTAGE * BUFB)     // 98304 B

__device__ __forceinline__ uint32_t sw_off(int row, int chunk) {
    return (uint32_t)(row * 64 + ((chunk ^ ((row >> 1) & 3)) << 4));
}

template <int WITH_BIAS>
__global__ __launch_bounds__(256, 2) void gemm_3xbf16(
    const __nv_bfloat16* __restrict__ Ahi, const __nv_bfloat16* __restrict__ Alo,
    const __nv_bfloat16* __restrict__ Bhi, const __nv_bfloat16* __restrict__ Blo,
    const float* __restrict__ bias, float* __restrict__ C, int N)
{
    extern __shared__ unsigned char dsmem[];
    const uint32_t sbase = smem_u32(dsmem);

    const int tid    = threadIdx.x;
    const int lane   = tid & 31;
    const int wid    = tid >> 5;
    const int warp_m = wid >> 1;       // 0..3
    const int warp_n = wid & 1;        // 0..1
    const int bm = blockIdx.y * 128;
    const int bn = blockIdx.x * 128;

    // cp.async mapping: row = tid>>1 (0..127), 2 chunks of 16B per tile
    const int lrow = tid >> 1;
    const int seg0 = (tid & 1) * 2;
    const __nv_bfloat16* gAh = Ahi + (size_t)(bm + lrow) * EMB;
    const __nv_bfloat16* gAl = Alo + (size_t)(bm + lrow) * EMB;
    const __nv_bfloat16* gBh = Bhi + (size_t)(bn + lrow) * EMB;
    const __nv_bfloat16* gBl = Blo + (size_t)(bn + lrow) * EMB;
    const uint32_t so0 = sw_off(lrow, seg0);
    const uint32_t so1 = sw_off(lrow, seg0 + 1);

    auto load_chunk = [&](int ch, int buf) {
        const uint32_t dst = sbase + buf * BUFB;
        const int gb = ch * (BK * 2);
        cp_async16(dst + so0,             (const char*)gAh + gb + seg0 * 16);
        cp_async16(dst + so1,             (const char*)gAh + gb + seg0 * 16 + 16);
        cp_async16(dst + TILEB + so0,     (const char*)gAl + gb + seg0 * 16);
        cp_async16(dst + TILEB + so1,     (const char*)gAl + gb + seg0 * 16 + 16);
        cp_async16(dst + 2 * TILEB + so0, (const char*)gBh + gb + seg0 * 16);
        cp_async16(dst + 2 * TILEB + so1, (const char*)gBh + gb + seg0 * 16 + 16);
        cp_async16(dst + 3 * TILEB + so0, (const char*)gBl + gb + seg0 * 16);
        cp_async16(dst + 3 * TILEB + so1, (const char*)gBl + gb + seg0 * 16 + 16);
    };

    // ldsm lane geometry
    const int a_row = warp_m * 32 + (lane & 15);               // + mt*16
    const int a_ck0 = lane >> 4;                               // + kk*2
    const int b_row = warp_n * 64 + (lane & 7) + ((lane >> 4) << 3);  // + ng*16
    const int b_ck0 = (lane >> 3) & 1;                         // + kk*2

    float acc[2][8][4];
#pragma unroll
    for (int mt = 0; mt < 2; mt++)
#pragma unroll
        for (int nt = 0; nt < 8; nt++)
#pragma unroll
            for (int r = 0; r < 4; r++) acc[mt][nt][r] = 0.f;

    const int nchunk = EMB / BK;   // 16
    load_chunk(0, 0); cp_commit();
    load_chunk(1, 1); cp_commit();

    for (int i = 0; i < nchunk; i++) {
        cp_wait1();            // stage i landed (stage i+1 may still fly)
        __syncthreads();       // also: all warps done with buffer (i-1)%3
        if (i + 2 < nchunk) { load_chunk(i + 2, (i + 2) % NSTAGE); cp_commit(); }

        const uint32_t base = sbase + (i % NSTAGE) * BUFB;

#pragma unroll
        for (int kk = 0; kk < 2; kk++) {
            uint32_t ah[2][4], al[2][4];
#pragma unroll
            for (int mt = 0; mt < 2; mt++) {
                const int r = a_row + mt * 16;
                const uint32_t o = sw_off(r, a_ck0 + kk * 2);
                ldsm_x4(ah[mt], base + o);
                ldsm_x4(al[mt], base + TILEB + o);
            }
#pragma unroll
            for (int ng = 0; ng < 4; ng++) {
                const int r = b_row + ng * 16;
                const uint32_t o = sw_off(r, b_ck0 + kk * 2);
                uint32_t bh[4], bl[4];
                ldsm_x4(bh, base + 2 * TILEB + o);
                ldsm_x4(bl, base + 3 * TILEB + o);
#pragma unroll
                for (int j = 0; j < 2; j++) {
                    const int nt = 2 * ng + j;
#pragma unroll
                    for (int mt = 0; mt < 2; mt++) {
                        mma_bf16(acc[mt][nt], ah[mt], bh + 2 * j);
                        mma_bf16(acc[mt][nt], al[mt], bh + 2 * j);
                        mma_bf16(acc[mt][nt], ah[mt], bl + 2 * j);
                    }
                }
            }
        }
    }

    const int lr  = lane >> 2;
    const int lc2 = (lane & 3) * 2;
#pragma unroll
    for (int mt = 0; mt < 2; mt++) {
        const int row0 = bm + warp_m * 32 + mt * 16 + lr;
#pragma unroll
        for (int nt = 0; nt < 8; nt++) {
            const int col = bn + warp_n * 64 + nt * 8 + lc2;
            float2 v0 = make_float2(acc[mt][nt][0], acc[mt][nt][1]);
            float2 v1 = make_float2(acc[mt][nt][2], acc[mt][nt][3]);
            if (WITH_BIAS) {
                v0.x += bias[col]; v0.y += bias[col + 1];
                v1.x += bias[col]; v1.y += bias[col + 1];
            }
            *reinterpret_cast<float2*>(C + (size_t)row0 * N + col)       = v0;
            *reinterpret_cast<float2*>(C + (size_t)(row0 + 8) * N + col) = v1;
        }
    }
}

// ---------------------------------------------------------------------------
// Fused shift-gather + attention + inverse-shift scatter.
// part buffer aliased onto qs/ks (dead after scores) -> ~31KB smem, 7 CTAs/SM.
// ---------------------------------------------------------------------------
#define AST 36

__global__ __launch_bounds__(128) void attn_kernel(
    const float* __restrict__ bias_table,
    const int*   __restrict__ rel_index)
{
    const int b   = blockIdx.x;
    const int h   = blockIdx.y;
    const int tid = threadIdx.x;

    __shared__ float qk[2 * SEQ * AST];   // qs | ks ; reused as part[2*SEQ*HD]
    __shared__ float vs[SEQ * AST];
    __shared__ float sc[SEQ * SEQ];
    __shared__ int   srow[SEQ];

    float* qs   = qk;
    float* ks   = qk + SEQ * AST;
    float* part = qk;                     // 2*49*32 = 3136 <= 2*49*36 = 3528

    const int t = (b / NWIN) % FL;

    if (tid < SEQ) {
        const int i = tid / 7, j = tid % 7;
        const int s = c_shift[(i % 3) * 3 + (j % 3)];
        const int tsrc = (t - s + 2 * FL) % FL;
        srow[tid] = b + (tsrc - t) * NWIN;
    }
    __syncthreads();

    for (int idx = tid; idx < SEQ * 8; idx += 128) {
        const int n = idx >> 3, f = idx & 7;
        const size_t base = ((size_t)srow[n] * SEQ + n) * QKVN + h * HD + f * 4;
        const int sm = n * AST + f * 4;
        *reinterpret_cast<float4*>(&qs[sm]) = *reinterpret_cast<const float4*>(&g_qkv[base]);
        *reinterpret_cast<float4*>(&ks[sm]) = *reinterpret_cast<const float4*>(&g_qkv[base + EMB]);
        *reinterpret_cast<float4*>(&vs[sm]) = *reinterpret_cast<const float4*>(&g_qkv[base + 2 * EMB]);
    }
    __syncthreads();

    const float scale = 0.1767766952966369f;

    if (tid < 98) {
        const int m  = (tid < SEQ) ? tid : tid - SEQ;
        const int n0 = (tid < SEQ) ? 0 : 25;
        const int n1 = (tid < SEQ) ? 25 : SEQ;
        float kr[HD];
#pragma unroll
        for (int f = 0; f < 8; f++)
            *reinterpret_cast<float4*>(&kr[f * 4]) = *reinterpret_cast<const float4*>(&ks[m * AST + f * 4]);
        for (int n = n0; n < n1; n++) {
            float acc = 0.f;
#pragma unroll
            for (int f = 0; f < 8; f++) {
                float4 q4 = *reinterpret_cast<const float4*>(&qs[n * AST + f * 4]);
                acc += q4.x * kr[f * 4] + q4.y * kr[f * 4 + 1]
                     + q4.z * kr[f * 4 + 2] + q4.w * kr[f * 4 + 3];
            }
            sc[n * SEQ + m] = acc * scale + bias_table[rel_index[n * SEQ + m] * NH + h];
        }
    }
    __syncthreads();

    if (tid < SEQ) {
        float mx = -1e30f;
#pragma unroll 7
        for (int m = 0; m < SEQ; m++) mx = fmaxf(mx, sc[tid * SEQ + m]);
        float sum = 0.f;
#pragma unroll 7
        for (int m = 0; m < SEQ; m++) {
            const float e = __expf(sc[tid * SEQ + m] - mx);
            sc[tid * SEQ + m] = e;
            sum += e;
        }
        const float inv = 1.f / sum;
#pragma unroll 7
        for (int m = 0; m < SEQ; m++) sc[tid * SEQ + m] *= inv;
    }
    __syncthreads();   // scores/softmax done; qs/ks dead -> part may be written

    {
        const int c  = tid & 31;
        const int nh = (tid >> 5) & 1;
        const int mq = (tid >> 6) & 1;
        const int mb = mq * 25;
        const int mc = mq ? 24 : 25;
        const int n0 = nh * 25;
        const int n1 = nh ? SEQ : 25;
        float vr[25];
        for (int i = 0; i < mc; i++) vr[i] = vs[(mb + i) * AST + c];
        for (int n = n0; n < n1; n++) {
            float a = 0.f;
            for (int i = 0; i < mc; i++) a += sc[n * SEQ + mb + i] * vr[i];
            part[(mq * SEQ + n) * HD + c] = a;
        }
    }
    __syncthreads();

    for (int idx = tid; idx < SEQ * (HD / 2); idx += 128) {
        const int n = idx / (HD / 2);
        const int c = (idx % (HD / 2)) * 2;
        const float s0 = part[n * HD + c]     + part[(SEQ + n) * HD + c];
        const float s1 = part[n * HD + c + 1] + part[(SEQ + n) * HD + c + 1];
        const size_t off = ((size_t)srow[n] * SEQ + n) * EMB + h * HD + c;
        const __nv_bfloat16 h0 = __float2bfloat16_rn(s0);
        const __nv_bfloat16 h1 = __float2bfloat16_rn(s1);
        *reinterpret_cast<__nv_bfloat162*>(&g_ahi[off]) = __nv_bfloat162(h0, h1);
        *reinterpret_cast<__nv_bfloat162*>(&g_alo[off]) =
            __nv_bfloat162(__float2bfloat16_rn(s0 - __bfloat162float(h0)),
                           __float2bfloat16_rn(s1 - __bfloat162float(h1)));
    }
}

// ---------------------------------------------------------------------------
extern "C" void kernel_launch(void* const* d_in, const int* in_sizes, int n_in,
                              void* d_out, int out_size)
{
    const float* x          = (const float*)d_in[0];
    const float* qkv_w      = (const float*)d_in[1];
    const float* proj_w     = (const float*)d_in[2];
    const float* proj_b     = (const float*)d_in[3];
    const float* bias_table = (const float*)d_in[4];
    const int*   rel_index  = (const int*)d_in[5];
    float* out = (float*)d_out;

    float* qkvbuf = nullptr;
    __nv_bfloat16 *xhi, *xlo, *ahi, *alo, *w1hi, *w1lo, *w2hi, *w2lo;
    cudaGetSymbolAddress((void**)&qkvbuf, g_qkv);
    cudaGetSymbolAddress((void**)&xhi,  g_xhi);
    cudaGetSymbolAddress((void**)&xlo,  g_xlo);
    cudaGetSymbolAddress((void**)&ahi,  g_ahi);
    cudaGetSymbolAddress((void**)&alo,  g_alo);
    cudaGetSymbolAddress((void**)&w1hi, g_w1hi);
    cudaGetSymbolAddress((void**)&w1lo, g_w1lo);
    cudaGetSymbolAddress((void**)&w2hi, g_w2hi);
    cudaGetSymbolAddress((void**)&w2lo, g_w2lo);

    cudaFuncSetAttribute(gemm_3xbf16<0>, cudaFuncAttributeMaxDynamicSharedMemorySize, GSMEM);
    cudaFuncSetAttribute(gemm_3xbf16<1>, cudaFuncAttributeMaxDynamicSharedMemorySize, GSMEM);

    // Prepass: split inputs to hi/lo bf16
    {
        const int n4x = MROWS * EMB / 4;
        split_kernel<<<(n4x + 255) / 256, 256>>>(x, xhi, xlo, n4x);
        const int n4w1 = QKVN * EMB / 4;
        split_kernel<<<(n4w1 + 255) / 256, 256>>>(qkv_w, w1hi, w1lo, n4w1);
        const int n4w2 = EMB * EMB / 4;
        split_kernel<<<(n4w2 + 255) / 256, 256>>>(proj_w, w2hi, w2lo, n4w2);
    }

    // K1: qkv = x @ qkv_w^T
    {
        dim3 grid(QKVN / 128, MROWS / 128);
        gemm_3xbf16<0><<<grid, 256, GSMEM>>>(xhi, xlo, w1hi, w1lo, nullptr, qkvbuf, QKVN);
    }
    // K2: fused shift + attention + inverse shift (emits hi/lo bf16)
    {
        dim3 grid(BTOT, NH);
        attn_kernel<<<grid, 128>>>(bias_table, rel_index);
    }
    // K3: out = att @ proj_w^T + proj_b
    {
        dim3 grid(EMB / 128, MROWS / 128);
        gemm_3xbf16<1><<<grid, 256, GSMEM>>>(ahi, alo, w2hi, w2lo, proj_b, out, EMB);
    }
}

// round 12
// speedup vs baseline: 2.7608x; 1.0448x over previous
#include <cuda_runtime.h>
#include <cuda_bf16.h>
#include <cstdint>

// Problem constants
#define BTOT   4096
#define SEQ    49
#define EMB    512
#define NH     16
#define HD     32
#define FL     16
#define NWIN   64
#define QKVN   1536
#define MROWS  (BTOT*SEQ)   // 200704

// Scratch (static device globals)
__device__ float         g_qkv[(size_t)MROWS * QKVN];
__device__ __nv_bfloat16 g_xhi[(size_t)MROWS * EMB];
__device__ __nv_bfloat16 g_xlo[(size_t)MROWS * EMB];
__device__ __nv_bfloat16 g_ahi[(size_t)MROWS * EMB];
__device__ __nv_bfloat16 g_alo[(size_t)MROWS * EMB];
__device__ __nv_bfloat16 g_w1hi[QKVN * EMB];
__device__ __nv_bfloat16 g_w1lo[QKVN * EMB];
__device__ __nv_bfloat16 g_w2hi[EMB * EMB];
__device__ __nv_bfloat16 g_w2lo[EMB * EMB];

__constant__ int c_shift[9] = {-4, 1, 2, -1, 0, 3, -2, -3, 4};

// ---------------------------------------------------------------------------
__device__ __forceinline__ uint32_t smem_u32(const void* p) {
    uint32_t a;
    asm("{ .reg .u64 t; cvta.to.shared.u64 t, %1; cvt.u32.u64 %0, t; }" : "=r"(a) : "l"(p));
    return a;
}
__device__ __forceinline__ void cp_async16(uint32_t s, const void* g) {
    asm volatile("cp.async.cg.shared.global [%0], [%1], 16;\n" :: "r"(s), "l"(g));
}
__device__ __forceinline__ void cp_commit() { asm volatile("cp.async.commit_group;\n"); }
__device__ __forceinline__ void cp_wait1()  { asm volatile("cp.async.wait_group 1;\n"); }

__device__ __forceinline__ void mma_bf16(float* d, const uint32_t* a, const uint32_t* b) {
    asm volatile(
        "mma.sync.aligned.m16n8k16.row.col.f32.bf16.bf16.f32 "
        "{%0,%1,%2,%3}, {%4,%5,%6,%7}, {%8,%9}, {%0,%1,%2,%3};\n"
        : "+f"(d[0]), "+f"(d[1]), "+f"(d[2]), "+f"(d[3])
        : "r"(a[0]), "r"(a[1]), "r"(a[2]), "r"(a[3]), "r"(b[0]), "r"(b[1]));
}
__device__ __forceinline__ void ldsm_x4(uint32_t* r, uint32_t addr) {
    asm volatile("ldmatrix.sync.aligned.m8n8.x4.shared.b16 {%0,%1,%2,%3}, [%4];\n"
                 : "=r"(r[0]), "=r"(r[1]), "=r"(r[2]), "=r"(r[3]) : "r"(addr));
}

// ---------------------------------------------------------------------------
// Split fp32 -> (hi, lo) bf16
// ---------------------------------------------------------------------------
__global__ void split_kernel(const float* __restrict__ in,
                             __nv_bfloat16* __restrict__ hi,
                             __nv_bfloat16* __restrict__ lo, int n4)
{
    const int i = blockIdx.x * blockDim.x + threadIdx.x;
    if (i >= n4) return;
    float4 v = reinterpret_cast<const float4*>(in)[i];
    __nv_bfloat16 h0 = __float2bfloat16_rn(v.x);
    __nv_bfloat16 h1 = __float2bfloat16_rn(v.y);
    __nv_bfloat16 h2 = __float2bfloat16_rn(v.z);
    __nv_bfloat16 h3 = __float2bfloat16_rn(v.w);
    __nv_bfloat162* hp = reinterpret_cast<__nv_bfloat162*>(hi);
    __nv_bfloat162* lp = reinterpret_cast<__nv_bfloat162*>(lo);
    hp[2 * i]     = __nv_bfloat162(h0, h1);
    hp[2 * i + 1] = __nv_bfloat162(h2, h3);
    lp[2 * i]     = __nv_bfloat162(__float2bfloat16_rn(v.x - __bfloat162float(h0)),
                                   __float2bfloat16_rn(v.y - __bfloat162float(h1)));
    lp[2 * i + 1] = __nv_bfloat162(__float2bfloat16_rn(v.z - __bfloat162float(h2)),
                                   __float2bfloat16_rn(v.w - __bfloat162float(h3)));
}

// ---------------------------------------------------------------------------
// 3xBF16 tensor-core GEMM (NT). 128x128 CTA tile, BK=32, 8 warps (4x2),
// warp tile 32x64, m16n8k16 mma. XOR-swizzled 64B smem rows; 3-stage
// cp.async pipeline; 2 CTAs/SM. Warp-staggered kk order (kk ^ wid&1)
// desynchronizes ldsm crossbar bursts from mma phases.
// ---------------------------------------------------------------------------
#define BK     32
#define TILEB  (128 * 64)          // 8192 B per tile
#define BUFB   (4 * TILEB)         // Ahi, Alo, Bhi, Blo = 32768 B
#define NSTAGE 3
#define GSMEM  (NSTAGE * BUFB)     // 98304 B

__device__ __forceinline__ uint32_t sw_off(int row, int chunk) {
    return (uint32_t)(row * 64 + ((chunk ^ ((row >> 1) & 3)) << 4));
}

template <int WITH_BIAS>
__global__ __launch_bounds__(256, 2) void gemm_3xbf16(
    const __nv_bfloat16* __restrict__ Ahi, const __nv_bfloat16* __restrict__ Alo,
    const __nv_bfloat16* __restrict__ Bhi, const __nv_bfloat16* __restrict__ Blo,
    const float* __restrict__ bias, float* __restrict__ C, int N)
{
    extern __shared__ unsigned char dsmem[];
    const uint32_t sbase = smem_u32(dsmem);

    const int tid    = threadIdx.x;
    const int lane   = tid & 31;
    const int wid    = tid >> 5;
    const int warp_m = wid >> 1;       // 0..3
    const int warp_n = wid & 1;        // 0..1
    const int kswap  = wid & 1;        // stagger kk order per warp
    const int bm = blockIdx.y * 128;
    const int bn = blockIdx.x * 128;

    // cp.async mapping: row = tid>>1 (0..127), 2 chunks of 16B per tile
    const int lrow = tid >> 1;
    const int seg0 = (tid & 1) * 2;
    const __nv_bfloat16* gAh = Ahi + (size_t)(bm + lrow) * EMB;
    const __nv_bfloat16* gAl = Alo + (size_t)(bm + lrow) * EMB;
    const __nv_bfloat16* gBh = Bhi + (size_t)(bn + lrow) * EMB;
    const __nv_bfloat16* gBl = Blo + (size_t)(bn + lrow) * EMB;
    const uint32_t so0 = sw_off(lrow, seg0);
    const uint32_t so1 = sw_off(lrow, seg0 + 1);

    auto load_chunk = [&](int ch, int buf) {
        const uint32_t dst = sbase + buf * BUFB;
        const int gb = ch * (BK * 2);
        cp_async16(dst + so0,             (const char*)gAh + gb + seg0 * 16);
        cp_async16(dst + so1,             (const char*)gAh + gb + seg0 * 16 + 16);
        cp_async16(dst + TILEB + so0,     (const char*)gAl + gb + seg0 * 16);
        cp_async16(dst + TILEB + so1,     (const char*)gAl + gb + seg0 * 16 + 16);
        cp_async16(dst + 2 * TILEB + so0, (const char*)gBh + gb + seg0 * 16);
        cp_async16(dst + 2 * TILEB + so1, (const char*)gBh + gb + seg0 * 16 + 16);
        cp_async16(dst + 3 * TILEB + so0, (const char*)gBl + gb + seg0 * 16);
        cp_async16(dst + 3 * TILEB + so1, (const char*)gBl + gb + seg0 * 16 + 16);
    };

    // ldsm lane geometry
    const int a_row = warp_m * 32 + (lane & 15);                      // + mt*16
    const int a_ck0 = lane >> 4;                                      // + kk*2
    const int b_row = warp_n * 64 + (lane & 7) + ((lane >> 4) << 3);  // + ng*16
    const int b_ck0 = (lane >> 3) & 1;                                // + kk*2

    float acc[2][8][4];
#pragma unroll
    for (int mt = 0; mt < 2; mt++)
#pragma unroll
        for (int nt = 0; nt < 8; nt++)
#pragma unroll
            for (int r = 0; r < 4; r++) acc[mt][nt][r] = 0.f;

    const int nchunk = EMB / BK;   // 16
    load_chunk(0, 0); cp_commit();
    load_chunk(1, 1); cp_commit();

    for (int i = 0; i < nchunk; i++) {
        cp_wait1();
        __syncthreads();
        if (i + 2 < nchunk) { load_chunk(i + 2, (i + 2) % NSTAGE); cp_commit(); }

        const uint32_t base = sbase + (i % NSTAGE) * BUFB;

#pragma unroll
        for (int kkx = 0; kkx < 2; kkx++) {
            const int kk = kkx ^ kswap;    // warp-staggered k order
            uint32_t ah[2][4], al[2][4];
#pragma unroll
            for (int mt = 0; mt < 2; mt++) {
                const int r = a_row + mt * 16;
                const uint32_t o = sw_off(r, a_ck0 + kk * 2);
                ldsm_x4(ah[mt], base + o);
                ldsm_x4(al[mt], base + TILEB + o);
            }
#pragma unroll
            for (int ng = 0; ng < 4; ng++) {
                const int r = b_row + ng * 16;
                const uint32_t o = sw_off(r, b_ck0 + kk * 2);
                uint32_t bh[4], bl[4];
                ldsm_x4(bh, base + 2 * TILEB + o);
                ldsm_x4(bl, base + 3 * TILEB + o);
#pragma unroll
                for (int j = 0; j < 2; j++) {
                    const int nt = 2 * ng + j;
#pragma unroll
                    for (int mt = 0; mt < 2; mt++) {
                        mma_bf16(acc[mt][nt], ah[mt], bh + 2 * j);
                        mma_bf16(acc[mt][nt], al[mt], bh + 2 * j);
                        mma_bf16(acc[mt][nt], ah[mt], bl + 2 * j);
                    }
                }
            }
        }
    }

    const int lr  = lane >> 2;
    const int lc2 = (lane & 3) * 2;
#pragma unroll
    for (int mt = 0; mt < 2; mt++) {
        const int row0 = bm + warp_m * 32 + mt * 16 + lr;
#pragma unroll
        for (int nt = 0; nt < 8; nt++) {
            const int col = bn + warp_n * 64 + nt * 8 + lc2;
            float2 v0 = make_float2(acc[mt][nt][0], acc[mt][nt][1]);
            float2 v1 = make_float2(acc[mt][nt][2], acc[mt][nt][3]);
            if (WITH_BIAS) {
                v0.x += bias[col]; v0.y += bias[col + 1];
                v1.x += bias[col]; v1.y += bias[col + 1];
            }
            *reinterpret_cast<float2*>(C + (size_t)row0 * N + col)       = v0;
            *reinterpret_cast<float2*>(C + (size_t)(row0 + 8) * N + col) = v1;
        }
    }
}

// ---------------------------------------------------------------------------
// Fused shift-gather + attention + inverse-shift scatter.
// sc rows stride 52 (16B-aligned) -> float4 softmax + float4 PV prob loads.
// part buffer aliased onto qs/ks.
// ---------------------------------------------------------------------------
#define AST 36
#define SST 52   // scores row stride (floats): 49 data + 3 pad, 16B aligned

__global__ __launch_bounds__(128) void attn_kernel(
    const float* __restrict__ bias_table,
    const int*   __restrict__ rel_index)
{
    const int b   = blockIdx.x;
    const int h   = blockIdx.y;
    const int tid = threadIdx.x;

    __shared__ float qk[2 * SEQ * AST];   // qs | ks ; reused as part[2*SEQ*HD]
    __shared__ float vs[SEQ * AST];
    __shared__ __align__(16) float sc[SEQ * SST];
    __shared__ int   srow[SEQ];

    float* qs   = qk;
    float* ks   = qk + SEQ * AST;
    float* part = qk;                     // 2*49*32 = 3136 <= 3528

    const int t = (b / NWIN) % FL;

    if (tid < SEQ) {
        const int i = tid / 7, j = tid % 7;
        const int s = c_shift[(i % 3) * 3 + (j % 3)];
        const int tsrc = (t - s + 2 * FL) % FL;
        srow[tid] = b + (tsrc - t) * NWIN;
    }
    __syncthreads();

    for (int idx = tid; idx < SEQ * 8; idx += 128) {
        const int n = idx >> 3, f = idx & 7;
        const size_t base = ((size_t)srow[n] * SEQ + n) * QKVN + h * HD + f * 4;
        const int sm = n * AST + f * 4;
        *reinterpret_cast<float4*>(&qs[sm]) = *reinterpret_cast<const float4*>(&g_qkv[base]);
        *reinterpret_cast<float4*>(&ks[sm]) = *reinterpret_cast<const float4*>(&g_qkv[base + EMB]);
        *reinterpret_cast<float4*>(&vs[sm]) = *reinterpret_cast<const float4*>(&g_qkv[base + 2 * EMB]);
    }
    __syncthreads();

    const float scale = 0.1767766952966369f;

    // scores: threads 0..97: m = tid%49, n-half = tid/49; K col in registers
    if (tid < 98) {
        const int m  = (tid < SEQ) ? tid : tid - SEQ;
        const int n0 = (tid < SEQ) ? 0 : 25;
        const int n1 = (tid < SEQ) ? 25 : SEQ;
        float kr[HD];
#pragma unroll
        for (int f = 0; f < 8; f++)
            *reinterpret_cast<float4*>(&kr[f * 4]) = *reinterpret_cast<const float4*>(&ks[m * AST + f * 4]);
        for (int n = n0; n < n1; n++) {
            float acc = 0.f;
#pragma unroll
            for (int f = 0; f < 8; f++) {
                float4 q4 = *reinterpret_cast<const float4*>(&qs[n * AST + f * 4]);
                acc += q4.x * kr[f * 4] + q4.y * kr[f * 4 + 1]
                     + q4.z * kr[f * 4 + 2] + q4.w * kr[f * 4 + 3];
            }
            sc[n * SST + m] = acc * scale + bias_table[rel_index[n * SEQ + m] * NH + h];
        }
    }
    __syncthreads();

    // softmax per row (float4)
    if (tid < SEQ) {
        float* r = &sc[tid * SST];
        float mx = -1e30f;
#pragma unroll
        for (int f = 0; f < 12; f++) {
            float4 v = *reinterpret_cast<const float4*>(&r[f * 4]);
            mx = fmaxf(mx, fmaxf(fmaxf(v.x, v.y), fmaxf(v.z, v.w)));
        }
        mx = fmaxf(mx, r[48]);
        float sum = 0.f;
#pragma unroll
        for (int f = 0; f < 12; f++) {
            float4 v = *reinterpret_cast<float4*>(&r[f * 4]);
            v.x = __expf(v.x - mx); v.y = __expf(v.y - mx);
            v.z = __expf(v.z - mx); v.w = __expf(v.w - mx);
            sum += (v.x + v.y) + (v.z + v.w);
            *reinterpret_cast<float4*>(&r[f * 4]) = v;
        }
        float e48 = __expf(r[48] - mx);
        r[48] = e48; sum += e48;
        const float inv = 1.f / sum;
#pragma unroll
        for (int f = 0; f < 12; f++) {
            float4 v = *reinterpret_cast<float4*>(&r[f * 4]);
            v.x *= inv; v.y *= inv; v.z *= inv; v.w *= inv;
            *reinterpret_cast<float4*>(&r[f * 4]) = v;
        }
        r[48] *= inv;
    }
    __syncthreads();   // scores done; qs/ks dead -> part may be written

    // PV: thread = (mq, nh, c); m split 28/21 at float4 alignment
    {
        const int c  = tid & 31;
        const int nh = (tid >> 5) & 1;
        const int mq = (tid >> 6) & 1;
        const int mb = mq ? 28 : 0;
        const int mc = mq ? 21 : 28;
        const int n0 = nh * 25;
        const int n1 = nh ? SEQ : 25;
        float vr[28];
        for (int i = 0; i < mc; i++) vr[i] = vs[(mb + i) * AST + c];
        for (int n = n0; n < n1; n++) {
            const float* sp = &sc[n * SST + mb];
            float a = 0.f;
            if (mq == 0) {
#pragma unroll
                for (int f = 0; f < 7; f++) {
                    float4 p = *reinterpret_cast<const float4*>(&sp[f * 4]);
                    a += p.x * vr[f * 4] + p.y * vr[f * 4 + 1]
                       + p.z * vr[f * 4 + 2] + p.w * vr[f * 4 + 3];
                }
            } else {
#pragma unroll
                for (int f = 0; f < 5; f++) {
                    float4 p = *reinterpret_cast<const float4*>(&sp[f * 4]);
                    a += p.x * vr[f * 4] + p.y * vr[f * 4 + 1]
                       + p.z * vr[f * 4 + 2] + p.w * vr[f * 4 + 3];
                }
                a += sp[20] * vr[20];
            }
            part[(mq * SEQ + n) * HD + c] = a;
        }
    }
    __syncthreads();

    for (int idx = tid; idx < SEQ * (HD / 2); idx += 128) {
        const int n = idx / (HD / 2);
        const int c = (idx % (HD / 2)) * 2;
        const float s0 = part[n * HD + c]     + part[(SEQ + n) * HD + c];
        const float s1 = part[n * HD + c + 1] + part[(SEQ + n) * HD + c + 1];
        const size_t off = ((size_t)srow[n] * SEQ + n) * EMB + h * HD + c;
        const __nv_bfloat16 h0 = __float2bfloat16_rn(s0);
        const __nv_bfloat16 h1 = __float2bfloat16_rn(s1);
        *reinterpret_cast<__nv_bfloat162*>(&g_ahi[off]) = __nv_bfloat162(h0, h1);
        *reinterpret_cast<__nv_bfloat162*>(&g_alo[off]) =
            __nv_bfloat162(__float2bfloat16_rn(s0 - __bfloat162float(h0)),
                           __float2bfloat16_rn(s1 - __bfloat162float(h1)));
    }
}

// ---------------------------------------------------------------------------
extern "C" void kernel_launch(void* const* d_in, const int* in_sizes, int n_in,
                              void* d_out, int out_size)
{
    const float* x          = (const float*)d_in[0];
    const float* qkv_w      = (const float*)d_in[1];
    const float* proj_w     = (const float*)d_in[2];
    const float* proj_b     = (const float*)d_in[3];
    const float* bias_table = (const float*)d_in[4];
    const int*   rel_index  = (const int*)d_in[5];
    float* out = (float*)d_out;

    float* qkvbuf = nullptr;
    __nv_bfloat16 *xhi, *xlo, *ahi, *alo, *w1hi, *w1lo, *w2hi, *w2lo;
    cudaGetSymbolAddress((void**)&qkvbuf, g_qkv);
    cudaGetSymbolAddress((void**)&xhi,  g_xhi);
    cudaGetSymbolAddress((void**)&xlo,  g_xlo);
    cudaGetSymbolAddress((void**)&ahi,  g_ahi);
    cudaGetSymbolAddress((void**)&alo,  g_alo);
    cudaGetSymbolAddress((void**)&w1hi, g_w1hi);
    cudaGetSymbolAddress((void**)&w1lo, g_w1lo);
    cudaGetSymbolAddress((void**)&w2hi, g_w2hi);
    cudaGetSymbolAddress((void**)&w2lo, g_w2lo);

    cudaFuncSetAttribute(gemm_3xbf16<0>, cudaFuncAttributeMaxDynamicSharedMemorySize, GSMEM);
    cudaFuncSetAttribute(gemm_3xbf16<1>, cudaFuncAttributeMaxDynamicSharedMemorySize, GSMEM);

    // Prepass: split inputs to hi/lo bf16
    {
        const int n4x = MROWS * EMB / 4;
        split_kernel<<<(n4x + 255) / 256, 256>>>(x, xhi, xlo, n4x);
        const int n4w1 = QKVN * EMB / 4;
        split_kernel<<<(n4w1 + 255) / 256, 256>>>(qkv_w, w1hi, w1lo, n4w1);
        const int n4w2 = EMB * EMB / 4;
        split_kernel<<<(n4w2 + 255) / 256, 256>>>(proj_w, w2hi, w2lo, n4w2);
    }

    // K1: qkv = x @ qkv_w^T
    {
        dim3 grid(QKVN / 128, MROWS / 128);
        gemm_3xbf16<0><<<grid, 256, GSMEM>>>(xhi, xlo, w1hi, w1lo, nullptr, qkvbuf, QKVN);
    }
    // K2: fused shift + attention + inverse shift (emits hi/lo bf16)
    {
        dim3 grid(BTOT, NH);
        attn_kernel<<<grid, 128>>>(bias_table, rel_index);
    }
    // K3: out = att @ proj_w^T + proj_b
    {
        dim3 grid(EMB / 128, MROWS / 128);
        gemm_3xbf16<1><<<grid, 256, GSMEM>>>(ahi, alo, w2hi, w2lo, proj_b, out, EMB);
    }
}

// round 16
// speedup vs baseline: 2.9048x; 1.0521x over previous
#include <cuda_runtime.h>
#include <cuda_bf16.h>
#include <cstdint>

// Problem constants
#define BTOT   4096
#define SEQ    49
#define EMB    512
#define NH     16
#define HD     32
#define FL     16
#define NWIN   64
#define QKVN   1536
#define MROWS  (BTOT*SEQ)   // 200704

#define SSTG   52   // padded stride for expanded bias rows

// Scratch (static device globals)
__device__ float         g_qkv[(size_t)MROWS * QKVN];
__device__ float         g_bias[NH * SEQ * SSTG];     // expanded rel-pos bias
__device__ __nv_bfloat16 g_xhi[(size_t)MROWS * EMB];
__device__ __nv_bfloat16 g_xlo[(size_t)MROWS * EMB];
__device__ __nv_bfloat16 g_ahi[(size_t)MROWS * EMB];
__device__ __nv_bfloat16 g_alo[(size_t)MROWS * EMB];
__device__ __nv_bfloat16 g_w1hi[QKVN * EMB];
__device__ __nv_bfloat16 g_w1lo[QKVN * EMB];
__device__ __nv_bfloat16 g_w2hi[EMB * EMB];
__device__ __nv_bfloat16 g_w2lo[EMB * EMB];

__constant__ int c_shift[9] = {-4, 1, 2, -1, 0, 3, -2, -3, 4};

// ---------------------------------------------------------------------------
__device__ __forceinline__ uint32_t smem_u32(const void* p) {
    uint32_t a;
    asm("{ .reg .u64 t; cvta.to.shared.u64 t, %1; cvt.u32.u64 %0, t; }" : "=r"(a) : "l"(p));
    return a;
}
__device__ __forceinline__ void cp_async16(uint32_t s, const void* g) {
    asm volatile("cp.async.cg.shared.global [%0], [%1], 16;\n" :: "r"(s), "l"(g));
}
__device__ __forceinline__ void cp_commit() { asm volatile("cp.async.commit_group;\n"); }
__device__ __forceinline__ void cp_wait1()  { asm volatile("cp.async.wait_group 1;\n"); }

__device__ __forceinline__ void mma_bf16(float* d, const uint32_t* a, const uint32_t* b) {
    asm volatile(
        "mma.sync.aligned.m16n8k16.row.col.f32.bf16.bf16.f32 "
        "{%0,%1,%2,%3}, {%4,%5,%6,%7}, {%8,%9}, {%0,%1,%2,%3};\n"
        : "+f"(d[0]), "+f"(d[1]), "+f"(d[2]), "+f"(d[3])
        : "r"(a[0]), "r"(a[1]), "r"(a[2]), "r"(a[3]), "r"(b[0]), "r"(b[1]));
}
__device__ __forceinline__ void ldsm_x4(uint32_t* r, uint32_t addr) {
    asm volatile("ldmatrix.sync.aligned.m8n8.x4.shared.b16 {%0,%1,%2,%3}, [%4];\n"
                 : "=r"(r[0]), "=r"(r[1]), "=r"(r[2]), "=r"(r[3]) : "r"(addr));
}

// ---------------------------------------------------------------------------
// Split fp32 -> (hi, lo) bf16
// ---------------------------------------------------------------------------
__global__ void split_kernel(const float* __restrict__ in,
                             __nv_bfloat16* __restrict__ hi,
                             __nv_bfloat16* __restrict__ lo, int n4)
{
    const int i = blockIdx.x * blockDim.x + threadIdx.x;
    if (i >= n4) return;
    float4 v = reinterpret_cast<const float4*>(in)[i];
    __nv_bfloat16 h0 = __float2bfloat16_rn(v.x);
    __nv_bfloat16 h1 = __float2bfloat16_rn(v.y);
    __nv_bfloat16 h2 = __float2bfloat16_rn(v.z);
    __nv_bfloat16 h3 = __float2bfloat16_rn(v.w);
    __nv_bfloat162* hp = reinterpret_cast<__nv_bfloat162*>(hi);
    __nv_bfloat162* lp = reinterpret_cast<__nv_bfloat162*>(lo);
    hp[2 * i]     = __nv_bfloat162(h0, h1);
    hp[2 * i + 1] = __nv_bfloat162(h2, h3);
    lp[2 * i]     = __nv_bfloat162(__float2bfloat16_rn(v.x - __bfloat162float(h0)),
                                   __float2bfloat16_rn(v.y - __bfloat162float(h1)));
    lp[2 * i + 1] = __nv_bfloat162(__float2bfloat16_rn(v.z - __bfloat162float(h2)),
                                   __float2bfloat16_rn(v.w - __bfloat162float(h3)));
}

// ---------------------------------------------------------------------------
// Expand relative-position bias: g_bias[h][n][m] = table[rel_index[n,m]][h]
// ---------------------------------------------------------------------------
__global__ void bias_expand_kernel(const float* __restrict__ bias_table,
                                   const int*   __restrict__ rel_index)
{
    const int h = blockIdx.x;
    for (int idx = threadIdx.x; idx < SEQ * SEQ; idx += blockDim.x) {
        const int n = idx / SEQ, m = idx % SEQ;
        g_bias[(h * SEQ + n) * SSTG + m] = bias_table[rel_index[idx] * NH + h];
    }
}

// ---------------------------------------------------------------------------
// 3xBF16 tensor-core GEMM (NT). 128x128 CTA tile, BK=32, 8 warps (4x2),
// warp tile 32x64, m16n8k16 mma. XOR-swizzled 64B smem rows; 3-stage
// cp.async pipeline; 2 CTAs/SM.
// ---------------------------------------------------------------------------
#define BK     32
#define TILEB  (128 * 64)          // 8192 B per tile
#define BUFB   (4 * TILEB)         // Ahi, Alo, Bhi, Blo = 32768 B
#define NSTAGE 3
#define GSMEM  (NSTAGE * BUFB)     // 98304 B

__device__ __forceinline__ uint32_t sw_off(int row, int chunk) {
    return (uint32_t)(row * 64 + ((chunk ^ ((row >> 1) & 3)) << 4));
}

template <int WITH_BIAS>
__global__ __launch_bounds__(256, 2) void gemm_3xbf16(
    const __nv_bfloat16* __restrict__ Ahi, const __nv_bfloat16* __restrict__ Alo,
    const __nv_bfloat16* __restrict__ Bhi, const __nv_bfloat16* __restrict__ Blo,
    const float* __restrict__ bias, float* __restrict__ C, int N)
{
    extern __shared__ unsigned char dsmem[];
    const uint32_t sbase = smem_u32(dsmem);

    const int tid    = threadIdx.x;
    const int lane   = tid & 31;
    const int wid    = tid >> 5;
    const int warp_m = wid >> 1;       // 0..3
    const int warp_n = wid & 1;        // 0..1
    const int bm = blockIdx.y * 128;
    const int bn = blockIdx.x * 128;

    const int lrow = tid >> 1;
    const int seg0 = (tid & 1) * 2;
    const __nv_bfloat16* gAh = Ahi + (size_t)(bm + lrow) * EMB;
    const __nv_bfloat16* gAl = Alo + (size_t)(bm + lrow) * EMB;
    const __nv_bfloat16* gBh = Bhi + (size_t)(bn + lrow) * EMB;
    const __nv_bfloat16* gBl = Blo + (size_t)(bn + lrow) * EMB;
    const uint32_t so0 = sw_off(lrow, seg0);
    const uint32_t so1 = sw_off(lrow, seg0 + 1);

    auto load_chunk = [&](int ch, int buf) {
        const uint32_t dst = sbase + buf * BUFB;
        const int gb = ch * (BK * 2);
        cp_async16(dst + so0,             (const char*)gAh + gb + seg0 * 16);
        cp_async16(dst + so1,             (const char*)gAh + gb + seg0 * 16 + 16);
        cp_async16(dst + TILEB + so0,     (const char*)gAl + gb + seg0 * 16);
        cp_async16(dst + TILEB + so1,     (const char*)gAl + gb + seg0 * 16 + 16);
        cp_async16(dst + 2 * TILEB + so0, (const char*)gBh + gb + seg0 * 16);
        cp_async16(dst + 2 * TILEB + so1, (const char*)gBh + gb + seg0 * 16 + 16);
        cp_async16(dst + 3 * TILEB + so0, (const char*)gBl + gb + seg0 * 16);
        cp_async16(dst + 3 * TILEB + so1, (const char*)gBl + gb + seg0 * 16 + 16);
    };

    const int a_row = warp_m * 32 + (lane & 15);
    const int a_ck0 = lane >> 4;
    const int b_row = warp_n * 64 + (lane & 7) + ((lane >> 4) << 3);
    const int b_ck0 = (lane >> 3) & 1;

    float acc[2][8][4];
#pragma unroll
    for (int mt = 0; mt < 2; mt++)
#pragma unroll
        for (int nt = 0; nt < 8; nt++)
#pragma unroll
            for (int r = 0; r < 4; r++) acc[mt][nt][r] = 0.f;

    const int nchunk = EMB / BK;   // 16
    load_chunk(0, 0); cp_commit();
    load_chunk(1, 1); cp_commit();

    for (int i = 0; i < nchunk; i++) {
        cp_wait1();
        __syncthreads();
        if (i + 2 < nchunk) { load_chunk(i + 2, (i + 2) % NSTAGE); cp_commit(); }

        const uint32_t base = sbase + (i % NSTAGE) * BUFB;

#pragma unroll
        for (int kk = 0; kk < 2; kk++) {
            uint32_t ah[2][4], al[2][4];
#pragma unroll
            for (int mt = 0; mt < 2; mt++) {
                const int r = a_row + mt * 16;
                const uint32_t o = sw_off(r, a_ck0 + kk * 2);
                ldsm_x4(ah[mt], base + o);
                ldsm_x4(al[mt], base + TILEB + o);
            }
#pragma unroll
            for (int ng = 0; ng < 4; ng++) {
                const int r = b_row + ng * 16;
                const uint32_t o = sw_off(r, b_ck0 + kk * 2);
                uint32_t bh[4], bl[4];
                ldsm_x4(bh, base + 2 * TILEB + o);
                ldsm_x4(bl, base + 3 * TILEB + o);
#pragma unroll
                for (int j = 0; j < 2; j++) {
                    const int nt = 2 * ng + j;
#pragma unroll
                    for (int mt = 0; mt < 2; mt++) {
                        mma_bf16(acc[mt][nt], ah[mt], bh + 2 * j);
                        mma_bf16(acc[mt][nt], al[mt], bh + 2 * j);
                        mma_bf16(acc[mt][nt], ah[mt], bl + 2 * j);
                    }
                }
            }
        }
    }

    const int lr  = lane >> 2;
    const int lc2 = (lane & 3) * 2;
#pragma unroll
    for (int mt = 0; mt < 2; mt++) {
        const int row0 = bm + warp_m * 32 + mt * 16 + lr;
#pragma unroll
        for (int nt = 0; nt < 8; nt++) {
            const int col = bn + warp_n * 64 + nt * 8 + lc2;
            float2 v0 = make_float2(acc[mt][nt][0], acc[mt][nt][1]);
            float2 v1 = make_float2(acc[mt][nt][2], acc[mt][nt][3]);
            if (WITH_BIAS) {
                v0.x += bias[col]; v0.y += bias[col + 1];
                v1.x += bias[col]; v1.y += bias[col + 1];
            }
            *reinterpret_cast<float2*>(C + (size_t)row0 * N + col)       = v0;
            *reinterpret_cast<float2*>(C + (size_t)(row0 + 8) * N + col) = v1;
        }
    }
}

// ---------------------------------------------------------------------------
// Fused shift-gather + attention + inverse-shift scatter.
// Bias read from pre-expanded g_bias (L2-resident, no indirection).
// ---------------------------------------------------------------------------
#define AST 36
#define SST 52

__global__ __launch_bounds__(128) void attn_kernel()
{
    const int b   = blockIdx.x;
    const int h   = blockIdx.y;
    const int tid = threadIdx.x;

    __shared__ float qk[2 * SEQ * AST];   // qs | ks ; reused as part
    __shared__ float vs[SEQ * AST];
    __shared__ __align__(16) float sc[SEQ * SST];
    __shared__ int   srow[SEQ];

    float* qs   = qk;
    float* ks   = qk + SEQ * AST;
    float* part = qk;

    const int t = (b / NWIN) % FL;

    if (tid < SEQ) {
        const int i = tid / 7, j = tid % 7;
        const int s = c_shift[(i % 3) * 3 + (j % 3)];
        const int tsrc = (t - s + 2 * FL) % FL;
        srow[tid] = b + (tsrc - t) * NWIN;
    }
    __syncthreads();

    for (int idx = tid; idx < SEQ * 8; idx += 128) {
        const int n = idx >> 3, f = idx & 7;
        const size_t base = ((size_t)srow[n] * SEQ + n) * QKVN + h * HD + f * 4;
        const int sm = n * AST + f * 4;
        *reinterpret_cast<float4*>(&qs[sm]) = *reinterpret_cast<const float4*>(&g_qkv[base]);
        *reinterpret_cast<float4*>(&ks[sm]) = *reinterpret_cast<const float4*>(&g_qkv[base + EMB]);
        *reinterpret_cast<float4*>(&vs[sm]) = *reinterpret_cast<const float4*>(&g_qkv[base + 2 * EMB]);
    }
    __syncthreads();

    const float scale = 0.1767766952966369f;

    // scores: threads 0..97: m = tid%49, n-half = tid/49; K col in registers
    if (tid < 98) {
        const int m  = (tid < SEQ) ? tid : tid - SEQ;
        const int n0 = (tid < SEQ) ? 0 : 25;
        const int n1 = (tid < SEQ) ? 25 : SEQ;
        const float* bg = &g_bias[(h * SEQ) * SSTG + m];
        float kr[HD];
#pragma unroll
        for (int f = 0; f < 8; f++)
            *reinterpret_cast<float4*>(&kr[f * 4]) = *reinterpret_cast<const float4*>(&ks[m * AST + f * 4]);
        for (int n = n0; n < n1; n++) {
            float acc = 0.f;
#pragma unroll
            for (int f = 0; f < 8; f++) {
                float4 q4 = *reinterpret_cast<const float4*>(&qs[n * AST + f * 4]);
                acc += q4.x * kr[f * 4] + q4.y * kr[f * 4 + 1]
                     + q4.z * kr[f * 4 + 2] + q4.w * kr[f * 4 + 3];
            }
            sc[n * SST + m] = acc * scale + bg[n * SSTG];
        }
    }
    __syncthreads();

    // softmax per row (float4)
    if (tid < SEQ) {
        float* r = &sc[tid * SST];
        float mx = -1e30f;
#pragma unroll
        for (int f = 0; f < 12; f++) {
            float4 v = *reinterpret_cast<const float4*>(&r[f * 4]);
            mx = fmaxf(mx, fmaxf(fmaxf(v.x, v.y), fmaxf(v.z, v.w)));
        }
        mx = fmaxf(mx, r[48]);
        float sum = 0.f;
#pragma unroll
        for (int f = 0; f < 12; f++) {
            float4 v = *reinterpret_cast<float4*>(&r[f * 4]);
            v.x = __expf(v.x - mx); v.y = __expf(v.y - mx);
            v.z = __expf(v.z - mx); v.w = __expf(v.w - mx);
            sum += (v.x + v.y) + (v.z + v.w);
            *reinterpret_cast<float4*>(&r[f * 4]) = v;
        }
        float e48 = __expf(r[48] - mx);
        r[48] = e48; sum += e48;
        const float inv = 1.f / sum;
#pragma unroll
        for (int f = 0; f < 12; f++) {
            float4 v = *reinterpret_cast<float4*>(&r[f * 4]);
            v.x *= inv; v.y *= inv; v.z *= inv; v.w *= inv;
            *reinterpret_cast<float4*>(&r[f * 4]) = v;
        }
        r[48] *= inv;
    }
    __syncthreads();

    // PV: thread = (mq, nh, c); m split 28/21 at float4 alignment
    {
        const int c  = tid & 31;
        const int nh = (tid >> 5) & 1;
        const int mq = (tid >> 6) & 1;
        const int mb = mq ? 28 : 0;
        const int mc = mq ? 21 : 28;
        const int n0 = nh * 25;
        const int n1 = nh ? SEQ : 25;
        float vr[28];
        for (int i = 0; i < mc; i++) vr[i] = vs[(mb + i) * AST + c];
        for (int n = n0; n < n1; n++) {
            const float* sp = &sc[n * SST + mb];
            float a = 0.f;
            if (mq == 0) {
#pragma unroll
                for (int f = 0; f < 7; f++) {
                    float4 p = *reinterpret_cast<const float4*>(&sp[f * 4]);
                    a += p.x * vr[f * 4] + p.y * vr[f * 4 + 1]
                       + p.z * vr[f * 4 + 2] + p.w * vr[f * 4 + 3];
                }
            } else {
#pragma unroll
                for (int f = 0; f < 5; f++) {
                    float4 p = *reinterpret_cast<const float4*>(&sp[f * 4]);
                    a += p.x * vr[f * 4] + p.y * vr[f * 4 + 1]
                       + p.z * vr[f * 4 + 2] + p.w * vr[f * 4 + 3];
                }
                a += sp[20] * vr[20];
            }
            part[(mq * SEQ + n) * HD + c] = a;
        }
    }
    __syncthreads();

    for (int idx = tid; idx < SEQ * (HD / 2); idx += 128) {
        const int n = idx / (HD / 2);
        const int c = (idx % (HD / 2)) * 2;
        const float s0 = part[n * HD + c]     + part[(SEQ + n) * HD + c];
        const float s1 = part[n * HD + c + 1] + part[(SEQ + n) * HD + c + 1];
        const size_t off = ((size_t)srow[n] * SEQ + n) * EMB + h * HD + c;
        const __nv_bfloat16 h0 = __float2bfloat16_rn(s0);
        const __nv_bfloat16 h1 = __float2bfloat16_rn(s1);
        *reinterpret_cast<__nv_bfloat162*>(&g_ahi[off]) = __nv_bfloat162(h0, h1);
        *reinterpret_cast<__nv_bfloat162*>(&g_alo[off]) =
            __nv_bfloat162(__float2bfloat16_rn(s0 - __bfloat162float(h0)),
                           __float2bfloat16_rn(s1 - __bfloat162float(h1)));
    }
}

// ---------------------------------------------------------------------------
extern "C" void kernel_launch(void* const* d_in, const int* in_sizes, int n_in,
                              void* d_out, int out_size)
{
    const float* x          = (const float*)d_in[0];
    const float* qkv_w      = (const float*)d_in[1];
    const float* proj_w     = (const float*)d_in[2];
    const float* proj_b     = (const float*)d_in[3];
    const float* bias_table = (const float*)d_in[4];
    const int*   rel_index  = (const int*)d_in[5];
    float* out = (float*)d_out;

    float* qkvbuf = nullptr;
    __nv_bfloat16 *xhi, *xlo, *ahi, *alo, *w1hi, *w1lo, *w2hi, *w2lo;
    cudaGetSymbolAddress((void**)&qkvbuf, g_qkv);
    cudaGetSymbolAddress((void**)&xhi,  g_xhi);
    cudaGetSymbolAddress((void**)&xlo,  g_xlo);
    cudaGetSymbolAddress((void**)&ahi,  g_ahi);
    cudaGetSymbolAddress((void**)&alo,  g_alo);
    cudaGetSymbolAddress((void**)&w1hi, g_w1hi);
    cudaGetSymbolAddress((void**)&w1lo, g_w1lo);
    cudaGetSymbolAddress((void**)&w2hi, g_w2hi);
    cudaGetSymbolAddress((void**)&w2lo, g_w2lo);

    cudaFuncSetAttribute(gemm_3xbf16<0>, cudaFuncAttributeMaxDynamicSharedMemorySize, GSMEM);
    cudaFuncSetAttribute(gemm_3xbf16<1>, cudaFuncAttributeMaxDynamicSharedMemorySize, GSMEM);

    // Prepass: split inputs to hi/lo bf16 + expand rel-pos bias
    {
        const int n4x = MROWS * EMB / 4;
        split_kernel<<<(n4x + 255) / 256, 256>>>(x, xhi, xlo, n4x);
        const int n4w1 = QKVN * EMB / 4;
        split_kernel<<<(n4w1 + 255) / 256, 256>>>(qkv_w, w1hi, w1lo, n4w1);
        const int n4w2 = EMB * EMB / 4;
        split_kernel<<<(n4w2 + 255) / 256, 256>>>(proj_w, w2hi, w2lo, n4w2);
        bias_expand_kernel<<<NH, 128>>>(bias_table, rel_index);
    }

    // K1: qkv = x @ qkv_w^T
    {
        dim3 grid(QKVN / 128, MROWS / 128);
        gemm_3xbf16<0><<<grid, 256, GSMEM>>>(xhi, xlo, w1hi, w1lo, nullptr, qkvbuf, QKVN);
    }
    // K2: fused shift + attention + inverse shift (emits hi/lo bf16)
    {
        dim3 grid(BTOT, NH);
        attn_kernel<<<grid, 128>>>();
    }
    // K3: out = att @ proj_w^T + proj_b
    {
        dim3 grid(EMB / 128, MROWS / 128);
        gemm_3xbf16<1><<<grid, 256, GSMEM>>>(ahi, alo, w2hi, w2lo, proj_b, out, EMB);
    }
}